// round 3
// baseline (speedup 1.0000x reference)
#include <cuda_runtime.h>

// Problem constants (fixed by the dataset)
#define BB 1024   // batch
#define PP 128    // p
#define MM 127    // p-1 (= hidden dim h, = reduced index count)

// ---------------------------------------------------------------------------
// Scratch (static __device__ arrays — allocation-free per harness rules)
// ---------------------------------------------------------------------------
__device__ float g_U[MM * MM * MM];       // [t][s][k]  combined weight tensor (~8.2 MB)
__device__ float g_D[BB * MM * MM];       // [b][t][s]  row-difference vectors (66 MB)
__device__ float g_dz[BB * MM * MM];      // [b][t][k]  per-column z deltas    (66 MB)
__device__ float g_z0[BB * MM];           // [b][k]     z at column 0
__device__ float g_h[BB * PP * MM];       // [b][t][k]  relu(z_t)              (66.6 MB)
__device__ float g_t12n[BB * PP * MM];    // [b][t][s]  second-layer output    (66.6 MB)

// ---------------------------------------------------------------------------
// K1: build U[t][s][k] from W1.  V[r,s,k]=W1[(r*127+s)*127+k],
//     Vt[r,k]=W1[(127*127+r)*127+k], winf[k]=W1[(127*127+127)*127+k]
// ---------------------------------------------------------------------------
__global__ void k_buildU(const float* __restrict__ W1) {
    int t = blockIdx.x;          // 0..126
    int k = threadIdx.x;         // 0..127
    if (k >= MM) return;
    float winf = W1[(MM * MM + MM) * MM + k];
    for (int s = 0; s < MM; s++) {
        float u;
        if (s == t) {
            u = W1[(t * MM + t) * MM + k] - winf;
        } else {
            u = W1[(t * MM + s) * MM + k]
              + W1[(s * MM + t) * MM + k]
              - W1[(MM * MM + s) * MM + k];
        }
        g_U[(t * MM + s) * MM + k] = u;
    }
}

// ---------------------------------------------------------------------------
// K2: z0[b,k] = b1[k] + sum_{r,s} Theta[b,r+1,s+1]*V[r,s,k]
//                      + sum_r Theta[b,r+1,0]*Vt[r,k] + Theta[b,0,0]*winf[k]
// Block: (128, 2) threads; ty splits the s-range, 8 batches per block.
// ---------------------------------------------------------------------------
#define NB 8
__global__ void __launch_bounds__(256) k_z0k(const float* __restrict__ Theta,
                                             const float* __restrict__ W1,
                                             const float* __restrict__ b1) {
    __shared__ float th[NB][PP];
    __shared__ float red[NB][PP];
    int k  = threadIdx.x;        // 0..127 -> hidden unit
    int ty = threadIdx.y;        // 0 or 1
    int b0 = blockIdx.x * NB;

    float acc[NB];
#pragma unroll
    for (int nb = 0; nb < NB; nb++) acc[nb] = 0.f;

    int s_lo = ty ? 64 : 0;
    int s_hi = ty ? MM : 64;

    for (int r = 0; r < MM; r++) {
        __syncthreads();
        if (ty == 0) {
#pragma unroll
            for (int nb = 0; nb < NB; nb++)
                th[nb][k] = Theta[((b0 + nb) * PP + (r + 1)) * PP + k];
        }
        __syncthreads();
        if (k < MM) {
#pragma unroll 4
            for (int s = s_lo; s < s_hi; s++) {
                float w = W1[(r * MM + s) * MM + k];
#pragma unroll
                for (int nb = 0; nb < NB; nb++) acc[nb] += th[nb][s + 1] * w;
            }
        }
    }

    // t12 / t22 part: load column 0 of Theta (row index = k)
    __syncthreads();
    if (ty == 0) {
#pragma unroll
        for (int nb = 0; nb < NB; nb++)
            th[nb][k] = Theta[((b0 + nb) * PP + k) * PP];
    }
    __syncthreads();
    if (ty == 1 && k < MM) {
#pragma unroll 4
        for (int r = 0; r < MM; r++) {
            float w = W1[(MM * MM + r) * MM + k];
#pragma unroll
            for (int nb = 0; nb < NB; nb++) acc[nb] += th[nb][r + 1] * w;
        }
        float w = W1[(MM * MM + MM) * MM + k];
#pragma unroll
        for (int nb = 0; nb < NB; nb++) {
            acc[nb] += th[nb][0] * w;
            red[nb][k] = acc[nb];
        }
    }
    __syncthreads();
    if (ty == 0 && k < MM) {
        float bias = b1[k];
#pragma unroll
        for (int nb = 0; nb < NB; nb++)
            g_z0[(b0 + nb) * MM + k] = acc[nb] + red[nb][k] + bias;
    }
}

// ---------------------------------------------------------------------------
// K3: D'[b,t,s]  (difference of Theta rows t and t+1, shifted-index gather)
// ---------------------------------------------------------------------------
__global__ void k_Dk(const float* __restrict__ Theta) {
    int t = blockIdx.x;          // 0..126
    int b = blockIdx.y;
    int s = threadIdx.x;         // 0..127
    if (s >= MM) return;
    const float* Tb = Theta + b * PP * PP;
    float v;
    if (s == t) {
        v = Tb[t * PP + t] - Tb[(t + 1) * PP + (t + 1)];
    } else {
        int g = s + (s >= t);
        v = Tb[t * PP + g] - Tb[(t + 1) * PP + g];
    }
    g_D[(b * MM + t) * MM + s] = v;
}

// ---------------------------------------------------------------------------
// K4: dz[b,t,k] = sum_s D'[b,t,s] * U[t,s,k]
// Grid (t=127, b-tiles=8); block 256 threads, 128x128 output tile, k-chunk 32.
// ---------------------------------------------------------------------------
__global__ void __launch_bounds__(256, 2) k_dgemm() {
    __shared__ float Us[32 * 128];        // [s][k]
    __shared__ float Ds[32 * 132];        // [s][bb] padded
    int t  = blockIdx.x;
    int b0 = blockIdx.y * PP;
    int tid = threadIdx.x;
    int tx = tid & 15, ty = tid >> 4;

    float acc[8][8];
#pragma unroll
    for (int i = 0; i < 8; i++)
#pragma unroll
        for (int j = 0; j < 8; j++) acc[i][j] = 0.f;

    for (int s0 = 0; s0 < MM; s0 += 32) {
        int sc = MM - s0; if (sc > 32) sc = 32;
        __syncthreads();
        for (int i = tid; i < 32 * 128; i += 256) {
            int s = i >> 7, k = i & 127;
            Us[i] = (s < sc && k < MM) ? g_U[(t * MM + s0 + s) * MM + k] : 0.f;
        }
        for (int i = tid; i < 32 * 128; i += 256) {
            int s = i & 31, bb = i >> 5;
            Ds[s * 132 + bb] = (s < sc) ? g_D[((b0 + bb) * MM + t) * MM + s0 + s] : 0.f;
        }
        __syncthreads();
#pragma unroll 8
        for (int s = 0; s < 32; s++) {
            float a[8], bv[8];
#pragma unroll
            for (int j = 0; j < 8; j++) a[j]  = Ds[s * 132 + ty * 8 + j];
#pragma unroll
            for (int j = 0; j < 8; j++) bv[j] = Us[s * 128 + tx * 8 + j];
#pragma unroll
            for (int i = 0; i < 8; i++)
#pragma unroll
                for (int j = 0; j < 8; j++) acc[i][j] += a[i] * bv[j];
        }
    }
#pragma unroll
    for (int i = 0; i < 8; i++) {
        int bb = ty * 8 + i;
#pragma unroll
        for (int j = 0; j < 8; j++) {
            int k = tx * 8 + j;
            if (k < MM) g_dz[((b0 + bb) * MM + t) * MM + k] = acc[i][j];
        }
    }
}

// ---------------------------------------------------------------------------
// K5: prefix over t + ReLU:  h[b,t,k] = relu(z0[b,k] + sum_{c<t} dz[b,c,k])
// ---------------------------------------------------------------------------
__global__ void k_prefix() {
    int b = blockIdx.x, k = threadIdx.x;
    if (k >= MM) return;
    float z = g_z0[b * MM + k];
    g_h[(b * PP) * MM + k] = fmaxf(z, 0.f);
    for (int t = 1; t < PP; t++) {
        z += g_dz[(b * MM + t - 1) * MM + k];
        g_h[(b * PP + t) * MM + k] = fmaxf(z, 0.f);
    }
}

// ---------------------------------------------------------------------------
// K6: t12n[R,s] = sum_k h[R,k]*W2[k,s] + b2[s],  R = b*128 + t  (131072 rows)
// ---------------------------------------------------------------------------
__global__ void __launch_bounds__(256, 2) k_gemm2(const float* __restrict__ W2,
                                                  const float* __restrict__ b2) {
    __shared__ float W2s[32 * 128];      // [kk][ss]
    __shared__ float Hs[32 * 132];       // [kk][rr] padded
    int R0 = blockIdx.x * PP;
    int tid = threadIdx.x;
    int tx = tid & 15, ty = tid >> 4;

    float acc[8][8];
#pragma unroll
    for (int i = 0; i < 8; i++)
#pragma unroll
        for (int j = 0; j < 8; j++) acc[i][j] = 0.f;

    for (int k0 = 0; k0 < MM; k0 += 32) {
        int kc = MM - k0; if (kc > 32) kc = 32;
        __syncthreads();
        for (int i = tid; i < 32 * 128; i += 256) {
            int kk = i >> 7, ss = i & 127;
            W2s[i] = (kk < kc && ss < MM) ? W2[(k0 + kk) * MM + ss] : 0.f;
        }
        for (int i = tid; i < 32 * 128; i += 256) {
            int kk = i & 31, rr = i >> 5;
            Hs[kk * 132 + rr] = (kk < kc) ? g_h[(R0 + rr) * MM + k0 + kk] : 0.f;
        }
        __syncthreads();
#pragma unroll 8
        for (int kk = 0; kk < 32; kk++) {
            float a[8], bv[8];
#pragma unroll
            for (int j = 0; j < 8; j++) a[j]  = Hs[kk * 132 + ty * 8 + j];
#pragma unroll
            for (int j = 0; j < 8; j++) bv[j] = W2s[kk * 128 + tx * 8 + j];
#pragma unroll
            for (int i = 0; i < 8; i++)
#pragma unroll
                for (int j = 0; j < 8; j++) acc[i][j] += a[i] * bv[j];
        }
    }
#pragma unroll
    for (int i = 0; i < 8; i++) {
        int rr = ty * 8 + i;
#pragma unroll
        for (int j = 0; j < 8; j++) {
            int ss = tx * 8 + j;
            if (ss < MM) g_t12n[(R0 + rr) * MM + ss] = acc[i][j] + b2[ss];
        }
    }
}

// ---------------------------------------------------------------------------
// K7: out[b,i,j] = Theta[b,i,j]                        (i==j)
//                = Theta[b,i,j] + 129*(t12n[b,max][min] - Theta[b,min,max])
// ---------------------------------------------------------------------------
__global__ void k_out(const float* __restrict__ Theta, float* __restrict__ out) {
    int b = blockIdx.x;
    const float* Tb = Theta + b * PP * PP;
    float* Ob = out + b * PP * PP;
    for (int i = threadIdx.x; i < PP * PP; i += blockDim.x) {
        int r = i >> 7, c = i & 127;
        float th = Tb[i];
        float o;
        if (r == c) {
            o = th;
        } else {
            int T = r > c ? r : c;
            int m = r > c ? c : r;
            float tn = g_t12n[(b * PP + T) * MM + m];
            float um = Tb[m * PP + T];   // Theta[idx_T(m)=m, T]
            o = th + 129.f * (tn - um);
        }
        Ob[i] = o;
    }
}

// ---------------------------------------------------------------------------
// Launch: Theta, W1, b1, W2, b2 used; D1/d1/D2/d2 are dead code in the ref.
// ---------------------------------------------------------------------------
extern "C" void kernel_launch(void* const* d_in, const int* in_sizes, int n_in,
                              void* d_out, int out_size) {
    const float* Theta = (const float*)d_in[0];
    const float* W1    = (const float*)d_in[1];
    const float* b1    = (const float*)d_in[2];
    const float* W2    = (const float*)d_in[3];
    const float* b2    = (const float*)d_in[4];
    float* out = (float*)d_out;
    (void)in_sizes; (void)n_in; (void)out_size;

    k_buildU<<<MM, 128>>>(W1);
    k_z0k<<<BB / NB, dim3(128, 2)>>>(Theta, W1, b1);
    k_Dk<<<dim3(MM, BB), 128>>>(Theta);
    k_dgemm<<<dim3(MM, BB / PP), 256>>>();
    k_prefix<<<BB, 128>>>();
    k_gemm2<<<BB, 256>>>(W2, b2);
    k_out<<<BB, 256>>>(Theta, out);
}

// round 5
// speedup vs baseline: 1.9114x; 1.9114x over previous
#include <cuda_runtime.h>

#define BB 1024
#define PP 128
#define MM 127

// ---------------------------------------------------------------------------
// Static device scratch (allocation-free)
// ---------------------------------------------------------------------------
__device__ float g_Upad[127 * 127 * 128];     // [t][s][k-padded]  8.3 MB
__device__ float g_W1p[16384 * 128];          // [ij][k-padded]    8.4 MB
__device__ float g_z0p[32 * 1024 * 128];      // split-K partials 16.8 MB
__device__ float g_z0[1024 * 128];            // [b][k]
__device__ float g_dz[1024 * 127 * 127];      // [b][t][k]        66 MB
__device__ float g_h[1024 * 128 * 127];       // [b][t][k]        66.6 MB

// ---------------------------------------------------------------------------
// Build U[t][s][k] (k padded to 128): combined first-layer delta weights
// ---------------------------------------------------------------------------
__global__ void k_buildU(const float* __restrict__ W1) {
    int t = blockIdx.x;          // 0..126
    int k = threadIdx.x;         // 0..127
    float winf = (k < MM) ? W1[16256 * 127 + k] : 0.f;
    for (int s = 0; s < MM; s++) {
        float u = 0.f;
        if (k < MM) {
            if (s == t)
                u = W1[(t * 127 + t) * 127 + k] - winf;
            else
                u = W1[(t * 127 + s) * 127 + k]
                  + W1[(s * 127 + t) * 127 + k]
                  - W1[(16129 + s) * 127 + k];
        }
        g_Upad[(t * 127 + s) * 128 + k] = u;
    }
}

// ---------------------------------------------------------------------------
// Build W1p[ij][k]: weights arranged so z0 = Theta_flat @ W1p
// ---------------------------------------------------------------------------
__global__ void k_buildW1p(const float* __restrict__ W1) {
    int ij = blockIdx.x;         // 0..16383
    int k  = threadIdx.x;        // 0..127
    int i = ij >> 7, j = ij & 127;
    float v = 0.f;
    if (k < 127) {
        if (i >= 1 && j >= 1)      v = W1[((i - 1) * 127 + (j - 1)) * 127 + k];
        else if (i >= 1)           v = W1[(16129 + (i - 1)) * 127 + k];  // j==0
        else if (j == 0)           v = W1[16256 * 127 + k];              // i==j==0
    }
    g_W1p[ij * 128 + k] = v;
}

// ---------------------------------------------------------------------------
// z0 GEMM: [1024,16384] @ [16384,128], split-K=32. grid (8 mtiles, 32 splits)
// ---------------------------------------------------------------------------
__global__ void __launch_bounds__(256, 2) k_z0(const float* __restrict__ Theta) {
    extern __shared__ float sm[];
    float* As = sm;                 // 2 * 32*132
    float* Bs = sm + 2 * 32 * 132;  // 2 * 32*128
    const int tid = threadIdx.x, tx = tid & 15, ty = tid >> 4;
    const int b0 = blockIdx.x * 128;
    const int kbase = blockIdx.y * 512;

    float acc[8][8];
#pragma unroll
    for (int i = 0; i < 8; i++)
#pragma unroll
        for (int j = 0; j < 8; j++) acc[i][j] = 0.f;

    // prologue: chunk 0
#pragma unroll
    for (int p = 0; p < 16; p++) {
        int i = tid + p * 256;
        As[(i & 31) * 132 + (i >> 5)] = Theta[(b0 + (i >> 5)) * 16384 + kbase + (i & 31)];
    }
#pragma unroll
    for (int p = 0; p < 16; p++) {
        int i = tid + p * 256;
        Bs[i] = g_W1p[(kbase + (i >> 7)) * 128 + (i & 127)];
    }
    __syncthreads();

    float pa[16], pb[16];
    for (int c = 0; c < 16; c++) {
        if (c < 15) {
            int kc = kbase + (c + 1) * 32;
#pragma unroll
            for (int p = 0; p < 16; p++) {
                int i = tid + p * 256;
                pa[p] = Theta[(b0 + (i >> 5)) * 16384 + kc + (i & 31)];
            }
#pragma unroll
            for (int p = 0; p < 16; p++) {
                int i = tid + p * 256;
                pb[p] = g_W1p[(kc + (i >> 7)) * 128 + (i & 127)];
            }
        }
        const float* Ab = As + (c & 1) * (32 * 132);
        const float* Bb = Bs + (c & 1) * (32 * 128);
#pragma unroll 8
        for (int s = 0; s < 32; s++) {
            float a[8], bv[8];
            *(float4*)a        = *(const float4*)(Ab + s * 132 + ty * 8);
            *(float4*)(a + 4)  = *(const float4*)(Ab + s * 132 + ty * 8 + 4);
            *(float4*)bv       = *(const float4*)(Bb + s * 128 + tx * 8);
            *(float4*)(bv + 4) = *(const float4*)(Bb + s * 128 + tx * 8 + 4);
#pragma unroll
            for (int i = 0; i < 8; i++)
#pragma unroll
                for (int j = 0; j < 8; j++) acc[i][j] += a[i] * bv[j];
        }
        if (c < 15) {
            float* An = As + ((c + 1) & 1) * (32 * 132);
            float* Bn = Bs + ((c + 1) & 1) * (32 * 128);
#pragma unroll
            for (int p = 0; p < 16; p++) {
                int i = tid + p * 256;
                An[(i & 31) * 132 + (i >> 5)] = pa[p];
            }
#pragma unroll
            for (int p = 0; p < 16; p++) {
                int i = tid + p * 256;
                Bn[i] = pb[p];
            }
            __syncthreads();
        }
    }
    float* outp = g_z0p + (blockIdx.y * 1024 + b0) * 128;
#pragma unroll
    for (int i = 0; i < 8; i++)
#pragma unroll
        for (int j = 0; j < 8; j++)
            outp[(ty * 8 + i) * 128 + tx * 8 + j] = acc[i][j];
}

// ---------------------------------------------------------------------------
// reduce split-K partials + bias
// ---------------------------------------------------------------------------
__global__ void k_z0red(const float* __restrict__ b1) {
    int idx = blockIdx.x * 256 + threadIdx.x;   // 131072 total
    int k = idx & 127;
    float s = (k < 127) ? b1[k] : 0.f;
#pragma unroll
    for (int sp = 0; sp < 32; sp++) s += g_z0p[sp * 131072 + idx];
    g_z0[idx] = s;
}

// ---------------------------------------------------------------------------
// dz[b,t,k] = sum_s D[b,t,s]*U[t,s,k], D built on the fly from Theta rows.
// U_t resident in smem; D chunks double-buffered. grid (127, 8)
// NOTE: diagonal special case — D[b,t,t] = Theta[t,t] - Theta[t+1,t+1].
// ---------------------------------------------------------------------------
__global__ void __launch_bounds__(256, 2) k_dz(const float* __restrict__ Theta) {
    extern __shared__ float sm[];
    float* Us = sm;            // 128*128 (rows 127 zeroed)
    float* Ds = sm + 16384;    // 2 * 32*132
    const int tid = threadIdx.x, tx = tid & 15, ty = tid >> 4;
    const int t = blockIdx.x, b0 = blockIdx.y * 128;

    // load U_t (vectorized)
    {
        const float4* Usrc = (const float4*)(g_Upad + t * 16256);
        float4* Ud = (float4*)Us;
        for (int i = tid; i < 4064; i += 256) Ud[i] = Usrc[i];
        for (int i = 16256 + tid; i < 16384; i += 256) Us[i] = 0.f;
    }

    auto loadD = [&](int c, int p) -> float {
        int i = tid + p * 256;
        int s = i & 31, bb = i >> 5;
        int sg = c * 32 + s;
        if (sg >= 127) return 0.f;
        const float* Tb = Theta + (b0 + bb) * 16384;
        if (sg == t)   // diagonal: Theta[t,t] - Theta[t+1,t+1]
            return Tb[(t << 7) + t] - Tb[((t + 1) << 7) + (t + 1)];
        int g = sg + (sg >= t);
        return Tb[(t << 7) + g] - Tb[((t + 1) << 7) + g];
    };

#pragma unroll
    for (int p = 0; p < 16; p++) {
        int i = tid + p * 256;
        Ds[(i & 31) * 132 + (i >> 5)] = loadD(0, p);
    }
    __syncthreads();

    float acc[8][8];
#pragma unroll
    for (int i = 0; i < 8; i++)
#pragma unroll
        for (int j = 0; j < 8; j++) acc[i][j] = 0.f;

    float pre[16];
    for (int c = 0; c < 4; c++) {
        if (c < 3) {
#pragma unroll
            for (int p = 0; p < 16; p++) pre[p] = loadD(c + 1, p);
        }
        const float* Db = Ds + (c & 1) * 4224;
        const float* Ub = Us + c * 32 * 128;
#pragma unroll 8
        for (int s = 0; s < 32; s++) {
            float a[8], bv[8];
            *(float4*)a        = *(const float4*)(Db + s * 132 + ty * 8);
            *(float4*)(a + 4)  = *(const float4*)(Db + s * 132 + ty * 8 + 4);
            *(float4*)bv       = *(const float4*)(Ub + s * 128 + tx * 8);
            *(float4*)(bv + 4) = *(const float4*)(Ub + s * 128 + tx * 8 + 4);
#pragma unroll
            for (int i = 0; i < 8; i++)
#pragma unroll
                for (int j = 0; j < 8; j++) acc[i][j] += a[i] * bv[j];
        }
        if (c < 3) {
            float* Dn = Ds + ((c + 1) & 1) * 4224;
#pragma unroll
            for (int p = 0; p < 16; p++) {
                int i = tid + p * 256;
                Dn[(i & 31) * 132 + (i >> 5)] = pre[p];
            }
            __syncthreads();
        }
    }
#pragma unroll
    for (int i = 0; i < 8; i++) {
        int bb = b0 + ty * 8 + i;
#pragma unroll
        for (int j = 0; j < 8; j++) {
            int k = tx * 8 + j;
            if (k < 127) g_dz[(bb * 127 + t) * 127 + k] = acc[i][j];
        }
    }
}

// ---------------------------------------------------------------------------
// prefix over t + ReLU
// ---------------------------------------------------------------------------
__global__ void k_prefix() {
    int b = blockIdx.x, k = threadIdx.x;
    if (k >= 127) return;
    float z = g_z0[b * 128 + k];
    float* hp = g_h + b * 128 * 127;
    const float* dzp = g_dz + b * 127 * 127;
    hp[k] = fmaxf(z, 0.f);
#pragma unroll 4
    for (int t = 1; t < 128; t++) {
        z += dzp[(t - 1) * 127 + k];
        hp[t * 127 + k] = fmaxf(z, 0.f);
    }
}

// ---------------------------------------------------------------------------
// gemm2 (h @ W2 + b2) fused with final out assembly. One block per batch.
// W2 resident in smem (reused as t12n stage tile after compute).
// ---------------------------------------------------------------------------
__global__ void __launch_bounds__(256, 2) k_g2out(const float* __restrict__ Theta,
                                                  const float* __restrict__ W2,
                                                  const float* __restrict__ b2,
                                                  float* __restrict__ out) {
    extern __shared__ float sm[];
    float* W2s = sm;            // 16512 floats: W2 [0,16384), later stage [128][129]
    float* Hs  = sm + 16512;    // 2 * 32*132
    const int tid = threadIdx.x, tx = tid & 15, ty = tid >> 4;
    const int b = blockIdx.x;
    const float* hb = g_h + b * 128 * 127;

    float b2v[8];
#pragma unroll
    for (int j = 0; j < 8; j++) {
        int ss = tx * 8 + j;
        b2v[j] = (ss < 127) ? b2[ss] : 0.f;
    }

    for (int i = tid; i < 16384; i += 256) {
        int kk = i >> 7, ss = i & 127;
        W2s[i] = (kk < 127 && ss < 127) ? W2[kk * 127 + ss] : 0.f;
    }

    auto loadH = [&](int c, int p) -> float {
        int i = tid + p * 256;
        int kk = i & 31, rr = i >> 5;
        int kg = c * 32 + kk;
        return (kg < 127) ? hb[rr * 127 + kg] : 0.f;
    };

#pragma unroll
    for (int p = 0; p < 16; p++) {
        int i = tid + p * 256;
        Hs[(i & 31) * 132 + (i >> 5)] = loadH(0, p);
    }
    __syncthreads();

    float acc[8][8];
#pragma unroll
    for (int i = 0; i < 8; i++)
#pragma unroll
        for (int j = 0; j < 8; j++) acc[i][j] = 0.f;

    float pre[16];
    for (int c = 0; c < 4; c++) {
        if (c < 3) {
#pragma unroll
            for (int p = 0; p < 16; p++) pre[p] = loadH(c + 1, p);
        }
        const float* Hb = Hs + (c & 1) * 4224;
        const float* Wb = W2s + c * 32 * 128;
#pragma unroll 8
        for (int s = 0; s < 32; s++) {
            float a[8], bv[8];
            *(float4*)a        = *(const float4*)(Hb + s * 132 + ty * 8);
            *(float4*)(a + 4)  = *(const float4*)(Hb + s * 132 + ty * 8 + 4);
            *(float4*)bv       = *(const float4*)(Wb + s * 128 + tx * 8);
            *(float4*)(bv + 4) = *(const float4*)(Wb + s * 128 + tx * 8 + 4);
#pragma unroll
            for (int i = 0; i < 8; i++)
#pragma unroll
                for (int j = 0; j < 8; j++) acc[i][j] += a[i] * bv[j];
        }
        if (c < 3) {
            float* Hn = Hs + ((c + 1) & 1) * 4224;
#pragma unroll
            for (int p = 0; p < 16; p++) {
                int i = tid + p * 256;
                Hn[(i & 31) * 132 + (i >> 5)] = pre[p];
            }
            __syncthreads();
        }
    }
    __syncthreads();   // all W2s reads done before reuse as stage

    // stage t12n tile (pad 129 -> conflict-free transposed reads)
#pragma unroll
    for (int i = 0; i < 8; i++)
#pragma unroll
        for (int j = 0; j < 8; j++)
            W2s[(ty * 8 + i) * 129 + tx * 8 + j] = acc[i][j] + b2v[j];
    __syncthreads();

    // final: out[b,r,c] = Theta + 129*(t12n[max][min] - Theta[min,max]); diag = Theta
    const float* Tb = Theta + b * 16384;
    float* Ob = out + b * 16384;
    for (int idx = tid; idx < 16384; idx += 256) {
        int r = idx >> 7, c = idx & 127;
        float th = Tb[idx];
        float o;
        if (r == c) {
            o = th;
        } else {
            int T = r > c ? r : c;
            int m = r < c ? r : c;
            float tn = W2s[T * 129 + m];
            float um = Tb[m * 128 + T];
            o = th + 129.f * (tn - um);
        }
        Ob[idx] = o;
    }
}

// ---------------------------------------------------------------------------
// Launch
// ---------------------------------------------------------------------------
extern "C" void kernel_launch(void* const* d_in, const int* in_sizes, int n_in,
                              void* d_out, int out_size) {
    const float* Theta = (const float*)d_in[0];
    const float* W1    = (const float*)d_in[1];
    const float* b1    = (const float*)d_in[2];
    const float* W2    = (const float*)d_in[3];
    const float* b2    = (const float*)d_in[4];
    float* out = (float*)d_out;
    (void)in_sizes; (void)n_in; (void)out_size;

    const int SM_Z0 = (2 * 32 * 132 + 2 * 32 * 128) * 4;     // 66560
    const int SM_DZ = (16384 + 2 * 32 * 132) * 4;            // 99328
    const int SM_G2 = (16512 + 2 * 32 * 132) * 4;            // 99840
    cudaFuncSetAttribute(k_z0,    cudaFuncAttributeMaxDynamicSharedMemorySize, SM_Z0);
    cudaFuncSetAttribute(k_dz,    cudaFuncAttributeMaxDynamicSharedMemorySize, SM_DZ);
    cudaFuncSetAttribute(k_g2out, cudaFuncAttributeMaxDynamicSharedMemorySize, SM_G2);

    k_buildU<<<127, 128>>>(W1);
    k_buildW1p<<<16384, 128>>>(W1);
    k_z0<<<dim3(8, 32), 256, SM_Z0>>>(Theta);
    k_z0red<<<512, 256>>>(b1);
    k_dz<<<dim3(127, 8), 256, SM_DZ>>>(Theta);
    k_prefix<<<1024, 128>>>();
    k_g2out<<<1024, 256, SM_G2>>>(Theta, W2, b2, out);
}

// round 6
// speedup vs baseline: 2.2467x; 1.1754x over previous
#include <cuda_runtime.h>

#define BB 1024
#define PP 128
#define MM 127

// ---------------------------------------------------------------------------
// Static device scratch (allocation-free). dz/h K-dim padded to 128.
// ---------------------------------------------------------------------------
__device__ float g_Upad[127 * 127 * 128];     // [t][s][k-pad]   8.3 MB
__device__ float g_W1p[16384 * 128];          // [ij][k-pad]     8.4 MB
__device__ float g_z0p[32 * 1024 * 128];      // split-K partials
__device__ float g_z0[1024 * 128];            // [b][k-pad]
__device__ float g_dz[1024 * 127 * 128];      // [b][t][k-pad]  66.6 MB
__device__ float g_h[1024 * 128 * 128];       // [b][t][k-pad]  67 MB

// ---------------------------------------------------------------------------
// f32x2 packed-FMA micro kernel helpers
// ---------------------------------------------------------------------------
__device__ __forceinline__ unsigned long long pack2(float x, float y) {
    unsigned long long u;
    asm("mov.b64 %0, {%1, %2};" : "=l"(u) : "r"(__float_as_uint(x)), "r"(__float_as_uint(y)));
    return u;
}
__device__ __forceinline__ unsigned long long dup2(float x) {
    unsigned long long u;
    asm("mov.b64 %0, {%1, %1};" : "=l"(u) : "r"(__float_as_uint(x)));
    return u;
}
__device__ __forceinline__ void unpack2(unsigned long long u, float& lo, float& hi) {
    unsigned int a, b;
    asm("mov.b64 {%0, %1}, %2;" : "=r"(a), "=r"(b) : "l"(u));
    lo = __uint_as_float(a); hi = __uint_as_float(b);
}
__device__ __forceinline__ void fma2(unsigned long long& d,
                                     unsigned long long a, unsigned long long b) {
    asm("fma.rn.f32x2 %0, %1, %2, %0;" : "+l"(d) : "l"(a), "l"(b));
}

// One s-step of the 128x128 outer-product tile.
// acc2[i2][j]: row-pair (ty*8+2*i2, +1), col tx*8+j.
__device__ __forceinline__ void mma_step(unsigned long long acc2[4][8],
                                         const float* __restrict__ Arow,
                                         const float* __restrict__ Brow) {
    float4 a0 = *(const float4*)(Arow);
    float4 a1 = *(const float4*)(Arow + 4);
    float4 b0 = *(const float4*)(Brow);
    float4 b1 = *(const float4*)(Brow + 4);
    unsigned long long a2[4], bd[8];
    a2[0] = pack2(a0.x, a0.y); a2[1] = pack2(a0.z, a0.w);
    a2[2] = pack2(a1.x, a1.y); a2[3] = pack2(a1.z, a1.w);
    bd[0] = dup2(b0.x); bd[1] = dup2(b0.y); bd[2] = dup2(b0.z); bd[3] = dup2(b0.w);
    bd[4] = dup2(b1.x); bd[5] = dup2(b1.y); bd[6] = dup2(b1.z); bd[7] = dup2(b1.w);
#pragma unroll
    for (int i2 = 0; i2 < 4; i2++)
#pragma unroll
        for (int j = 0; j < 8; j++) fma2(acc2[i2][j], a2[i2], bd[j]);
}

// ---------------------------------------------------------------------------
// Build U[t][s][k] (k padded to 128)
// ---------------------------------------------------------------------------
__global__ void k_buildU(const float* __restrict__ W1) {
    int t = blockIdx.x, k = threadIdx.x;
    float winf = (k < MM) ? W1[16256 * 127 + k] : 0.f;
    for (int s = 0; s < MM; s++) {
        float u = 0.f;
        if (k < MM) {
            if (s == t)
                u = W1[(t * 127 + t) * 127 + k] - winf;
            else
                u = W1[(t * 127 + s) * 127 + k]
                  + W1[(s * 127 + t) * 127 + k]
                  - W1[(16129 + s) * 127 + k];
        }
        g_Upad[(t * 127 + s) * 128 + k] = u;
    }
}

// ---------------------------------------------------------------------------
// Build W1p[ij][k]: z0 = Theta_flat @ W1p
// ---------------------------------------------------------------------------
__global__ void k_buildW1p(const float* __restrict__ W1) {
    int ij = blockIdx.x, k = threadIdx.x;
    int i = ij >> 7, j = ij & 127;
    float v = 0.f;
    if (k < 127) {
        if (i >= 1 && j >= 1)      v = W1[((i - 1) * 127 + (j - 1)) * 127 + k];
        else if (i >= 1)           v = W1[(16129 + (i - 1)) * 127 + k];
        else if (j == 0)           v = W1[16256 * 127 + k];
    }
    g_W1p[ij * 128 + k] = v;
}

// ---------------------------------------------------------------------------
// z0 GEMM: [1024,16384]@[16384,128], split-K=32. grid (8, 32)
// ---------------------------------------------------------------------------
__global__ void __launch_bounds__(256, 2) k_z0(const float* __restrict__ Theta) {
    extern __shared__ float sm[];
    float* As = sm;                 // 2 * 32*132
    float* Bs = sm + 2 * 32 * 132;  // 2 * 32*128
    const int tid = threadIdx.x, tx = tid & 15, ty = tid >> 4;
    const int b0 = blockIdx.x * 128;
    const int kbase = blockIdx.y * 512;

    unsigned long long acc2[4][8];
#pragma unroll
    for (int i = 0; i < 4; i++)
#pragma unroll
        for (int j = 0; j < 8; j++) acc2[i][j] = 0ull;

#pragma unroll
    for (int p = 0; p < 16; p++) {
        int i = tid + p * 256;
        As[(i & 31) * 132 + (i >> 5)] = Theta[(b0 + (i >> 5)) * 16384 + kbase + (i & 31)];
    }
#pragma unroll
    for (int p = 0; p < 16; p++) {
        int i = tid + p * 256;
        Bs[i] = g_W1p[(kbase + (i >> 7)) * 128 + (i & 127)];
    }
    __syncthreads();

    float pa[16], pb[16];
    for (int c = 0; c < 16; c++) {
        if (c < 15) {
            int kc = kbase + (c + 1) * 32;
#pragma unroll
            for (int p = 0; p < 16; p++) {
                int i = tid + p * 256;
                pa[p] = Theta[(b0 + (i >> 5)) * 16384 + kc + (i & 31)];
            }
#pragma unroll
            for (int p = 0; p < 16; p++) {
                int i = tid + p * 256;
                pb[p] = g_W1p[(kc + (i >> 7)) * 128 + (i & 127)];
            }
        }
        const float* Ab = As + (c & 1) * (32 * 132);
        const float* Bb = Bs + (c & 1) * (32 * 128);
#pragma unroll 8
        for (int s = 0; s < 32; s++)
            mma_step(acc2, Ab + s * 132 + ty * 8, Bb + s * 128 + tx * 8);
        if (c < 15) {
            float* An = As + ((c + 1) & 1) * (32 * 132);
            float* Bn = Bs + ((c + 1) & 1) * (32 * 128);
#pragma unroll
            for (int p = 0; p < 16; p++) {
                int i = tid + p * 256;
                An[(i & 31) * 132 + (i >> 5)] = pa[p];
            }
#pragma unroll
            for (int p = 0; p < 16; p++) {
                int i = tid + p * 256;
                Bn[i] = pb[p];
            }
            __syncthreads();
        }
    }
    float* outp = g_z0p + (blockIdx.y * 1024 + b0) * 128;
#pragma unroll
    for (int i2 = 0; i2 < 4; i2++) {
        float lo[8], hi[8];
#pragma unroll
        for (int j = 0; j < 8; j++) unpack2(acc2[i2][j], lo[j], hi[j]);
        float* p0 = outp + (ty * 8 + 2 * i2) * 128 + tx * 8;
        float* p1 = p0 + 128;
        *(float4*)p0       = make_float4(lo[0], lo[1], lo[2], lo[3]);
        *(float4*)(p0 + 4) = make_float4(lo[4], lo[5], lo[6], lo[7]);
        *(float4*)p1       = make_float4(hi[0], hi[1], hi[2], hi[3]);
        *(float4*)(p1 + 4) = make_float4(hi[4], hi[5], hi[6], hi[7]);
    }
}

// ---------------------------------------------------------------------------
// reduce split-K partials + bias
// ---------------------------------------------------------------------------
__global__ void k_z0red(const float* __restrict__ b1) {
    int idx = blockIdx.x * 256 + threadIdx.x;
    int k = idx & 127;
    float s = (k < 127) ? b1[k] : 0.f;
#pragma unroll
    for (int sp = 0; sp < 32; sp++) s += g_z0p[sp * 131072 + idx];
    g_z0[idx] = s;
}

// ---------------------------------------------------------------------------
// dz[b,t,k] = sum_s D[b,t,s]*U[t,s,k]; D on the fly (diag special case!)
// ---------------------------------------------------------------------------
__global__ void __launch_bounds__(256, 2) k_dz(const float* __restrict__ Theta) {
    extern __shared__ float sm[];
    float* Us = sm;            // 128*128
    float* Ds = sm + 16384;    // 2 * 32*132
    const int tid = threadIdx.x, tx = tid & 15, ty = tid >> 4;
    const int t = blockIdx.x, b0 = blockIdx.y * 128;

    {
        const float4* Usrc = (const float4*)(g_Upad + t * 16256);
        float4* Ud = (float4*)Us;
        for (int i = tid; i < 4064; i += 256) Ud[i] = Usrc[i];
        for (int i = 16256 + tid; i < 16384; i += 256) Us[i] = 0.f;
    }

    auto loadD = [&](int c, int p) -> float {
        int i = tid + p * 256;
        int s = i & 31, bb = i >> 5;
        int sg = c * 32 + s;
        if (sg >= 127) return 0.f;
        const float* Tb = Theta + (b0 + bb) * 16384;
        if (sg == t)
            return Tb[(t << 7) + t] - Tb[((t + 1) << 7) + (t + 1)];
        int g = sg + (sg >= t);
        return Tb[(t << 7) + g] - Tb[((t + 1) << 7) + g];
    };

#pragma unroll
    for (int p = 0; p < 16; p++) {
        int i = tid + p * 256;
        Ds[(i & 31) * 132 + (i >> 5)] = loadD(0, p);
    }
    __syncthreads();

    unsigned long long acc2[4][8];
#pragma unroll
    for (int i = 0; i < 4; i++)
#pragma unroll
        for (int j = 0; j < 8; j++) acc2[i][j] = 0ull;

    float pre[16];
    for (int c = 0; c < 4; c++) {
        if (c < 3) {
#pragma unroll
            for (int p = 0; p < 16; p++) pre[p] = loadD(c + 1, p);
        }
        const float* Db = Ds + (c & 1) * 4224;
        const float* Ub = Us + c * 32 * 128;
#pragma unroll 8
        for (int s = 0; s < 32; s++)
            mma_step(acc2, Db + s * 132 + ty * 8, Ub + s * 128 + tx * 8);
        if (c < 3) {
            float* Dn = Ds + ((c + 1) & 1) * 4224;
#pragma unroll
            for (int p = 0; p < 16; p++) {
                int i = tid + p * 256;
                Dn[(i & 31) * 132 + (i >> 5)] = pre[p];
            }
            __syncthreads();
        }
    }
#pragma unroll
    for (int i2 = 0; i2 < 4; i2++) {
        float lo[8], hi[8];
#pragma unroll
        for (int j = 0; j < 8; j++) unpack2(acc2[i2][j], lo[j], hi[j]);
        int bb0 = b0 + ty * 8 + 2 * i2;
        float* p0 = g_dz + (bb0 * 127 + t) * 128 + tx * 8;
        float* p1 = g_dz + ((bb0 + 1) * 127 + t) * 128 + tx * 8;
        *(float4*)p0       = make_float4(lo[0], lo[1], lo[2], lo[3]);
        *(float4*)(p0 + 4) = make_float4(lo[4], lo[5], lo[6], lo[7]);
        *(float4*)p1       = make_float4(hi[0], hi[1], hi[2], hi[3]);
        *(float4*)(p1 + 4) = make_float4(hi[4], hi[5], hi[6], hi[7]);
    }
}

// ---------------------------------------------------------------------------
// prefix over t + ReLU (float4 vectorized; 8 batches per 256-thread block)
// ---------------------------------------------------------------------------
__global__ void k_prefix() {
    int tid = threadIdx.x;
    int b = blockIdx.x * 8 + (tid >> 5);
    int k4 = tid & 31;
    float4 z = *(const float4*)(g_z0 + b * 128 + k4 * 4);
    float4* hp = (float4*)(g_h + b * 128 * 128) + k4;
    const float4* dzp = (const float4*)(g_dz + b * 127 * 128) + k4;
    hp[0] = make_float4(fmaxf(z.x, 0.f), fmaxf(z.y, 0.f), fmaxf(z.z, 0.f), fmaxf(z.w, 0.f));
#pragma unroll 4
    for (int t = 1; t < 128; t++) {
        float4 d = dzp[(t - 1) * 32];
        z.x += d.x; z.y += d.y; z.z += d.z; z.w += d.w;
        hp[t * 32] = make_float4(fmaxf(z.x, 0.f), fmaxf(z.y, 0.f),
                                 fmaxf(z.z, 0.f), fmaxf(z.w, 0.f));
    }
}

// ---------------------------------------------------------------------------
// gemm2 (h @ W2 + b2) fused with final out assembly (uses Theta symmetry:
// out = th + 129*(t12n - th) off-diag, th on diag). One block per batch.
// ---------------------------------------------------------------------------
__global__ void __launch_bounds__(256, 2) k_g2out(const float* __restrict__ Theta,
                                                  const float* __restrict__ W2,
                                                  const float* __restrict__ b2,
                                                  float* __restrict__ out) {
    extern __shared__ float sm[];
    float* W2s = sm;            // 16512: W2 [0,16384), later stage [128][129]
    float* Hs  = sm + 16512;    // 2 * 32*132
    const int tid = threadIdx.x, tx = tid & 15, ty = tid >> 4;
    const int b = blockIdx.x;
    const float* hb = g_h + b * 128 * 128;

    float b2v[8];
#pragma unroll
    for (int j = 0; j < 8; j++) {
        int ss = tx * 8 + j;
        b2v[j] = (ss < 127) ? b2[ss] : 0.f;
    }

    for (int i = tid; i < 16384; i += 256) {
        int kk = i >> 7, ss = i & 127;
        W2s[i] = (kk < 127 && ss < 127) ? W2[kk * 127 + ss] : 0.f;
    }

    auto loadH = [&](int c, int p) -> float {
        int i = tid + p * 256;
        int kk = i & 31, rr = i >> 5;
        return hb[rr * 128 + c * 32 + kk];   // h col 127 is exactly 0 (padded pipeline)
    };

#pragma unroll
    for (int p = 0; p < 16; p++) {
        int i = tid + p * 256;
        Hs[(i & 31) * 132 + (i >> 5)] = loadH(0, p);
    }
    __syncthreads();

    unsigned long long acc2[4][8];
#pragma unroll
    for (int i = 0; i < 4; i++)
#pragma unroll
        for (int j = 0; j < 8; j++) acc2[i][j] = 0ull;

    float pre[16];
    for (int c = 0; c < 4; c++) {
        if (c < 3) {
#pragma unroll
            for (int p = 0; p < 16; p++) pre[p] = loadH(c + 1, p);
        }
        const float* Hb = Hs + (c & 1) * 4224;
        const float* Wb = W2s + c * 32 * 128;
#pragma unroll 8
        for (int s = 0; s < 32; s++)
            mma_step(acc2, Hb + s * 132 + ty * 8, Wb + s * 128 + tx * 8);
        if (c < 3) {
            float* Hn = Hs + ((c + 1) & 1) * 4224;
#pragma unroll
            for (int p = 0; p < 16; p++) {
                int i = tid + p * 256;
                Hn[(i & 31) * 132 + (i >> 5)] = pre[p];
            }
            __syncthreads();
        }
    }
    __syncthreads();   // all W2s reads done before reuse as stage

    // stage t12n tile (pad 129 -> conflict-free transposed reads)
#pragma unroll
    for (int i2 = 0; i2 < 4; i2++) {
        float lo[8], hi[8];
#pragma unroll
        for (int j = 0; j < 8; j++) unpack2(acc2[i2][j], lo[j], hi[j]);
        int r0 = ty * 8 + 2 * i2;
#pragma unroll
        for (int j = 0; j < 8; j++) {
            W2s[r0 * 129 + tx * 8 + j]       = lo[j] + b2v[j];
            W2s[(r0 + 1) * 129 + tx * 8 + j] = hi[j] + b2v[j];
        }
    }
    __syncthreads();

    // out[b,r,c]: diag = th; off-diag = th + 129*(t12n[max][min] - th)
    const float* Tb = Theta + b * 16384;
    float* Ob = out + b * 16384;
    for (int idx4 = tid; idx4 < 4096; idx4 += 256) {
        int r = idx4 >> 5;
        int c0 = (idx4 & 31) * 4;
        float4 th4 = *(const float4*)(Tb + r * 128 + c0);
        float th[4] = {th4.x, th4.y, th4.z, th4.w};
        float o[4];
#pragma unroll
        for (int l = 0; l < 4; l++) {
            int c = c0 + l;
            if (r == c) {
                o[l] = th[l];
            } else {
                int T = r > c ? r : c;
                int m = r < c ? r : c;
                float tn = W2s[T * 129 + m];
                o[l] = th[l] + 129.f * (tn - th[l]);
            }
        }
        *(float4*)(Ob + r * 128 + c0) = make_float4(o[0], o[1], o[2], o[3]);
    }
}

// ---------------------------------------------------------------------------
// Launch
// ---------------------------------------------------------------------------
extern "C" void kernel_launch(void* const* d_in, const int* in_sizes, int n_in,
                              void* d_out, int out_size) {
    const float* Theta = (const float*)d_in[0];
    const float* W1    = (const float*)d_in[1];
    const float* b1    = (const float*)d_in[2];
    const float* W2    = (const float*)d_in[3];
    const float* b2    = (const float*)d_in[4];
    float* out = (float*)d_out;
    (void)in_sizes; (void)n_in; (void)out_size;

    const int SM_Z0 = (2 * 32 * 132 + 2 * 32 * 128) * 4;     // 66560
    const int SM_DZ = (16384 + 2 * 32 * 132) * 4;            // 99328
    const int SM_G2 = (16512 + 2 * 32 * 132) * 4;            // 99840
    cudaFuncSetAttribute(k_z0,    cudaFuncAttributeMaxDynamicSharedMemorySize, SM_Z0);
    cudaFuncSetAttribute(k_dz,    cudaFuncAttributeMaxDynamicSharedMemorySize, SM_DZ);
    cudaFuncSetAttribute(k_g2out, cudaFuncAttributeMaxDynamicSharedMemorySize, SM_G2);

    k_buildU<<<127, 128>>>(W1);
    k_buildW1p<<<16384, 128>>>(W1);
    k_z0<<<dim3(8, 32), 256, SM_Z0>>>(Theta);
    k_z0red<<<512, 256>>>(b1);
    k_dz<<<dim3(127, 8), 256, SM_DZ>>>(Theta);
    k_prefix<<<128, 256>>>();
    k_g2out<<<1024, 256, SM_G2>>>(Theta, W2, b2, out);
}

// round 7
// speedup vs baseline: 2.6143x; 1.1636x over previous
#include <cuda_runtime.h>

#define BB 1024
#define PP 128
#define MM 127

typedef unsigned long long ull;

// ---------------------------------------------------------------------------
// Static device scratch (allocation-free)
// ---------------------------------------------------------------------------
__device__ float g_Upad[127 * 127 * 128];     // [t][s][k-pad]   8.3 MB
__device__ float g_W1p[16384 * 128];          // [ij][k-pad]     8.4 MB
__device__ float g_z0p[32 * 1024 * 128];      // split-K partials
__device__ float g_z0[1024 * 128];            // [b][k-pad]
__device__ float g_dz[1024 * 127 * 128];      // [b][t][k-pad]  66.6 MB

// ---------------------------------------------------------------------------
// f32x2 packed-FMA helpers. A-side pairs come straight from 16B smem loads
// (consecutive rows adjacent in the transposed tiles) — no pack movs.
// ---------------------------------------------------------------------------
__device__ __forceinline__ ull dup2(float x) {
    ull u;
    asm("mov.b64 %0, {%1, %1};" : "=l"(u) : "r"(__float_as_uint(x)));
    return u;
}
__device__ __forceinline__ void unpack2(ull u, float& lo, float& hi) {
    unsigned int a, b;
    asm("mov.b64 {%0, %1}, %2;" : "=r"(a), "=r"(b) : "l"(u));
    lo = __uint_as_float(a); hi = __uint_as_float(b);
}
__device__ __forceinline__ void fma2(ull& d, ull a, ull b) {
    asm("fma.rn.f32x2 %0, %1, %2, %0;" : "+l"(d) : "l"(a), "l"(b));
}

// acc2[i2][j]: row-pair (ty*8+2*i2, +1), col tx*8+j. Arow/Brow 16B-aligned.
__device__ __forceinline__ void mma_step(ull acc2[4][8],
                                         const float* __restrict__ Arow,
                                         const float* __restrict__ Brow) {
    ulonglong2 aA = *(const ulonglong2*)(Arow);       // packed (a0,a1),(a2,a3)
    ulonglong2 aB = *(const ulonglong2*)(Arow + 4);   // packed (a4,a5),(a6,a7)
    float4 b0 = *(const float4*)(Brow);
    float4 b1 = *(const float4*)(Brow + 4);
    ull a2[4] = {aA.x, aA.y, aB.x, aB.y};
    ull bd[8];
    bd[0] = dup2(b0.x); bd[1] = dup2(b0.y); bd[2] = dup2(b0.z); bd[3] = dup2(b0.w);
    bd[4] = dup2(b1.x); bd[5] = dup2(b1.y); bd[6] = dup2(b1.z); bd[7] = dup2(b1.w);
#pragma unroll
    for (int i2 = 0; i2 < 4; i2++)
#pragma unroll
        for (int j = 0; j < 8; j++) fma2(acc2[i2][j], a2[i2], bd[j]);
}

// ---------------------------------------------------------------------------
// Build U[t][s][k] (k padded to 128). grid (127, 4) — s-range split.
// ---------------------------------------------------------------------------
__global__ void k_buildU(const float* __restrict__ W1) {
    int t = blockIdx.x, k = threadIdx.x;
    int s0 = blockIdx.y * 32;
    int s1 = s0 + 32 < 127 ? s0 + 32 : 127;
    float winf = (k < MM) ? W1[16256 * 127 + k] : 0.f;
    for (int s = s0; s < s1; s++) {
        float u = 0.f;
        if (k < MM) {
            if (s == t)
                u = W1[(t * 127 + t) * 127 + k] - winf;
            else
                u = W1[(t * 127 + s) * 127 + k]
                  + W1[(s * 127 + t) * 127 + k]
                  - W1[(16129 + s) * 127 + k];
        }
        g_Upad[(t * 127 + s) * 128 + k] = u;
    }
}

// ---------------------------------------------------------------------------
// Build W1p[ij][k]: z0 = Theta_flat @ W1p
// ---------------------------------------------------------------------------
__global__ void k_buildW1p(const float* __restrict__ W1) {
    int ij = blockIdx.x, k = threadIdx.x;
    int i = ij >> 7, j = ij & 127;
    float v = 0.f;
    if (k < 127) {
        if (i >= 1 && j >= 1)      v = W1[((i - 1) * 127 + (j - 1)) * 127 + k];
        else if (i >= 1)           v = W1[(16129 + (i - 1)) * 127 + k];
        else if (j == 0)           v = W1[16256 * 127 + k];
    }
    g_W1p[ij * 128 + k] = v;
}

// ---------------------------------------------------------------------------
// z0 GEMM: [1024,16384]@[16384,128], split-K=32. grid (8, 32)
// ---------------------------------------------------------------------------
__global__ void __launch_bounds__(256, 2) k_z0(const float* __restrict__ Theta) {
    extern __shared__ float sm[];
    float* As = sm;                 // 2 * 32*132
    float* Bs = sm + 2 * 32 * 132;  // 2 * 32*128
    const int tid = threadIdx.x, tx = tid & 15, ty = tid >> 4;
    const int b0 = blockIdx.x * 128;
    const int kbase = blockIdx.y * 512;

    ull acc2[4][8];
#pragma unroll
    for (int i = 0; i < 4; i++)
#pragma unroll
        for (int j = 0; j < 8; j++) acc2[i][j] = 0ull;

#pragma unroll
    for (int p = 0; p < 16; p++) {
        int i = tid + p * 256;
        As[(i & 31) * 132 + (i >> 5)] = Theta[(b0 + (i >> 5)) * 16384 + kbase + (i & 31)];
    }
#pragma unroll
    for (int p = 0; p < 16; p++) {
        int i = tid + p * 256;
        Bs[i] = g_W1p[(kbase + (i >> 7)) * 128 + (i & 127)];
    }
    __syncthreads();

    float pa[16], pb[16];
    for (int c = 0; c < 16; c++) {
        if (c < 15) {
            int kc = kbase + (c + 1) * 32;
#pragma unroll
            for (int p = 0; p < 16; p++) {
                int i = tid + p * 256;
                pa[p] = Theta[(b0 + (i >> 5)) * 16384 + kc + (i & 31)];
            }
#pragma unroll
            for (int p = 0; p < 16; p++) {
                int i = tid + p * 256;
                pb[p] = g_W1p[(kc + (i >> 7)) * 128 + (i & 127)];
            }
        }
        const float* Ab = As + (c & 1) * (32 * 132);
        const float* Bb = Bs + (c & 1) * (32 * 128);
#pragma unroll 8
        for (int s = 0; s < 32; s++)
            mma_step(acc2, Ab + s * 132 + ty * 8, Bb + s * 128 + tx * 8);
        if (c < 15) {
            float* An = As + ((c + 1) & 1) * (32 * 132);
            float* Bn = Bs + ((c + 1) & 1) * (32 * 128);
#pragma unroll
            for (int p = 0; p < 16; p++) {
                int i = tid + p * 256;
                An[(i & 31) * 132 + (i >> 5)] = pa[p];
            }
#pragma unroll
            for (int p = 0; p < 16; p++) {
                int i = tid + p * 256;
                Bn[i] = pb[p];
            }
            __syncthreads();
        }
    }
    float* outp = g_z0p + (blockIdx.y * 1024 + b0) * 128;
#pragma unroll
    for (int i2 = 0; i2 < 4; i2++) {
        float lo[8], hi[8];
#pragma unroll
        for (int j = 0; j < 8; j++) unpack2(acc2[i2][j], lo[j], hi[j]);
        float* p0 = outp + (ty * 8 + 2 * i2) * 128 + tx * 8;
        float* p1 = p0 + 128;
        *(float4*)p0       = make_float4(lo[0], lo[1], lo[2], lo[3]);
        *(float4*)(p0 + 4) = make_float4(lo[4], lo[5], lo[6], lo[7]);
        *(float4*)p1       = make_float4(hi[0], hi[1], hi[2], hi[3]);
        *(float4*)(p1 + 4) = make_float4(hi[4], hi[5], hi[6], hi[7]);
    }
}

// ---------------------------------------------------------------------------
// reduce split-K partials + bias
// ---------------------------------------------------------------------------
__global__ void k_z0red(const float* __restrict__ b1) {
    int idx = blockIdx.x * 256 + threadIdx.x;
    int k = idx & 127;
    float s = (k < 127) ? b1[k] : 0.f;
#pragma unroll
    for (int sp = 0; sp < 32; sp++) s += g_z0p[sp * 131072 + idx];
    g_z0[idx] = s;
}

// ---------------------------------------------------------------------------
// dz[b,t,k] = sum_s D[b,t,s]*U[t,s,k]; D on the fly (diag special case!)
// ---------------------------------------------------------------------------
__global__ void __launch_bounds__(256, 2) k_dz(const float* __restrict__ Theta) {
    extern __shared__ float sm[];
    float* Us = sm;            // 128*128
    float* Ds = sm + 16384;    // 2 * 32*132
    const int tid = threadIdx.x, tx = tid & 15, ty = tid >> 4;
    const int t = blockIdx.x, b0 = blockIdx.y * 128;

    {
        const float4* Usrc = (const float4*)(g_Upad + t * 16256);
        float4* Ud = (float4*)Us;
        for (int i = tid; i < 4064; i += 256) Ud[i] = Usrc[i];
        for (int i = 16256 + tid; i < 16384; i += 256) Us[i] = 0.f;
    }

    auto loadD = [&](int c, int p) -> float {
        int i = tid + p * 256;
        int s = i & 31, bb = i >> 5;
        int sg = c * 32 + s;
        if (sg >= 127) return 0.f;
        const float* Tb = Theta + (b0 + bb) * 16384;
        if (sg == t)
            return Tb[(t << 7) + t] - Tb[((t + 1) << 7) + (t + 1)];
        int g = sg + (sg >= t);
        return Tb[(t << 7) + g] - Tb[((t + 1) << 7) + g];
    };

#pragma unroll
    for (int p = 0; p < 16; p++) {
        int i = tid + p * 256;
        Ds[(i & 31) * 132 + (i >> 5)] = loadD(0, p);
    }
    __syncthreads();

    ull acc2[4][8];
#pragma unroll
    for (int i = 0; i < 4; i++)
#pragma unroll
        for (int j = 0; j < 8; j++) acc2[i][j] = 0ull;

    float pre[16];
    for (int c = 0; c < 4; c++) {
        if (c < 3) {
#pragma unroll
            for (int p = 0; p < 16; p++) pre[p] = loadD(c + 1, p);
        }
        const float* Db = Ds + (c & 1) * 4224;
        const float* Ub = Us + c * 32 * 128;
#pragma unroll 8
        for (int s = 0; s < 32; s++)
            mma_step(acc2, Db + s * 132 + ty * 8, Ub + s * 128 + tx * 8);
        if (c < 3) {
            float* Dn = Ds + ((c + 1) & 1) * 4224;
#pragma unroll
            for (int p = 0; p < 16; p++) {
                int i = tid + p * 256;
                Dn[(i & 31) * 132 + (i >> 5)] = pre[p];
            }
            __syncthreads();
        }
    }
#pragma unroll
    for (int i2 = 0; i2 < 4; i2++) {
        float lo[8], hi[8];
#pragma unroll
        for (int j = 0; j < 8; j++) unpack2(acc2[i2][j], lo[j], hi[j]);
        int bb0 = b0 + ty * 8 + 2 * i2;
        float* p0 = g_dz + (bb0 * 127 + t) * 128 + tx * 8;
        float* p1 = g_dz + ((bb0 + 1) * 127 + t) * 128 + tx * 8;
        *(float4*)p0       = make_float4(lo[0], lo[1], lo[2], lo[3]);
        *(float4*)(p0 + 4) = make_float4(lo[4], lo[5], lo[6], lo[7]);
        *(float4*)p1       = make_float4(hi[0], hi[1], hi[2], hi[3]);
        *(float4*)(p1 + 4) = make_float4(hi[4], hi[5], hi[6], hi[7]);
    }
}

// ---------------------------------------------------------------------------
// Fused: prefix+ReLU into smem h_T[k][t] (pad 132), GEMM h@W2 with W2
// streamed (double-buffered), bias, final out assembly (Theta symmetry).
// One block per batch. smem = 128*132 + 2*32*128 floats = 100352 B.
// ---------------------------------------------------------------------------
__global__ void __launch_bounds__(256, 2) k_g2out(const float* __restrict__ Theta,
                                                  const float* __restrict__ W2,
                                                  const float* __restrict__ b2,
                                                  float* __restrict__ out) {
    extern __shared__ float sm[];
    float* Ht = sm;              // [k][t] pad 132; later reused as t12n stage [r][132]
    float* Ws = sm + 128 * 132;  // 2 * 32*128 W2 chunks
    const int tid = threadIdx.x, tx = tid & 15, ty = tid >> 4;
    const int b = blockIdx.x;

    // Phase 1: threads 0-127 run the prefix+relu for k=tid; threads 128-255
    // load W2 chunk 0 into buffer 0.
    if (tid < 128) {
        int k = tid;
        float z = g_z0[b * 128 + k];
        const float* dzp = g_dz + b * 127 * 128 + k;
        Ht[k * 132] = fmaxf(z, 0.f);
#pragma unroll 4
        for (int t = 1; t < 128; t++) {
            z += dzp[(t - 1) * 128];
            Ht[k * 132 + t] = fmaxf(z, 0.f);
        }
    } else {
        int t2 = tid - 128;
#pragma unroll
        for (int p = 0; p < 32; p++) {
            int i = t2 + p * 128;           // 0..4095
            int kk = i >> 7, ss = i & 127;
            Ws[i] = (ss < 127) ? W2[kk * 127 + ss] : 0.f;   // kk<32 always valid
        }
    }
    __syncthreads();

    ull acc2[4][8];
#pragma unroll
    for (int i = 0; i < 4; i++)
#pragma unroll
        for (int j = 0; j < 8; j++) acc2[i][j] = 0ull;

    float pre[16];
    for (int c = 0; c < 4; c++) {
        if (c < 3) {
#pragma unroll
            for (int p = 0; p < 16; p++) {
                int i = tid + p * 256;
                int kk = (c + 1) * 32 + (i >> 7), ss = i & 127;
                pre[p] = (kk < 127 && ss < 127) ? W2[kk * 127 + ss] : 0.f;
            }
        }
        const float* Wb = Ws + (c & 1) * 4096;
#pragma unroll 8
        for (int s = 0; s < 32; s++)
            mma_step(acc2, Ht + (c * 32 + s) * 132 + ty * 8, Wb + s * 128 + tx * 8);
        if (c < 3) {
            float* Wn = Ws + ((c + 1) & 1) * 4096;
#pragma unroll
            for (int p = 0; p < 16; p++) {
                int i = tid + p * 256;
                Wn[i] = pre[p];
            }
            __syncthreads();
        }
    }
    __syncthreads();   // all Ht reads done before reuse as stage

    float b2v[8];
#pragma unroll
    for (int j = 0; j < 8; j++) {
        int ss = tx * 8 + j;
        b2v[j] = (ss < 127) ? b2[ss] : 0.f;
    }

    // stage t12n tile into Ht: [r][132] (rows r = t, cols = s)
#pragma unroll
    for (int i2 = 0; i2 < 4; i2++) {
        float lo[8], hi[8];
#pragma unroll
        for (int j = 0; j < 8; j++) unpack2(acc2[i2][j], lo[j], hi[j]);
        int r0 = ty * 8 + 2 * i2;
#pragma unroll
        for (int j = 0; j < 8; j++) {
            Ht[r0 * 132 + tx * 8 + j]       = lo[j] + b2v[j];
            Ht[(r0 + 1) * 132 + tx * 8 + j] = hi[j] + b2v[j];
        }
    }
    __syncthreads();

    // out[b,r,c]: diag = th; off-diag = th + 129*(t12n[max][min] - th)
    const float* Tb = Theta + b * 16384;
    float* Ob = out + b * 16384;
    for (int idx4 = tid; idx4 < 4096; idx4 += 256) {
        int r = idx4 >> 5;
        int c0 = (idx4 & 31) * 4;
        float4 th4 = *(const float4*)(Tb + r * 128 + c0);
        float th[4] = {th4.x, th4.y, th4.z, th4.w};
        float o[4];
#pragma unroll
        for (int l = 0; l < 4; l++) {
            int c = c0 + l;
            if (r == c) {
                o[l] = th[l];
            } else {
                int T = r > c ? r : c;
                int m = r < c ? r : c;
                float tn = Ht[T * 132 + m];
                o[l] = th[l] + 129.f * (tn - th[l]);
            }
        }
        *(float4*)(Ob + r * 128 + c0) = make_float4(o[0], o[1], o[2], o[3]);
    }
}

// ---------------------------------------------------------------------------
// Launch
// ---------------------------------------------------------------------------
extern "C" void kernel_launch(void* const* d_in, const int* in_sizes, int n_in,
                              void* d_out, int out_size) {
    const float* Theta = (const float*)d_in[0];
    const float* W1    = (const float*)d_in[1];
    const float* b1    = (const float*)d_in[2];
    const float* W2    = (const float*)d_in[3];
    const float* b2    = (const float*)d_in[4];
    float* out = (float*)d_out;
    (void)in_sizes; (void)n_in; (void)out_size;

    const int SM_Z0 = (2 * 32 * 132 + 2 * 32 * 128) * 4;     // 66560
    const int SM_DZ = (16384 + 2 * 32 * 132) * 4;            // 99328
    const int SM_G2 = (128 * 132 + 2 * 32 * 128) * 4;        // 100352
    cudaFuncSetAttribute(k_z0,    cudaFuncAttributeMaxDynamicSharedMemorySize, SM_Z0);
    cudaFuncSetAttribute(k_dz,    cudaFuncAttributeMaxDynamicSharedMemorySize, SM_DZ);
    cudaFuncSetAttribute(k_g2out, cudaFuncAttributeMaxDynamicSharedMemorySize, SM_G2);

    k_buildU<<<dim3(127, 4), 128>>>(W1);
    k_buildW1p<<<16384, 128>>>(W1);
    k_z0<<<dim3(8, 32), 256, SM_Z0>>>(Theta);
    k_z0red<<<512, 256>>>(b1);
    k_dz<<<dim3(127, 8), 256, SM_DZ>>>(Theta);
    k_g2out<<<1024, 256, SM_G2>>>(Theta, W2, b2, out);
}

// round 8
// speedup vs baseline: 2.8413x; 1.0869x over previous
#include <cuda_runtime.h>

#define BB 1024
#define PP 128
#define MM 127

typedef unsigned long long ull;

#define NPAIR 8256          // 128*129/2
#define KSPLIT 32
#define KPER 272            // per-split pair count (17 chunks of 16); 32*272 = 8704
#define NPAD (KSPLIT * KPER)

// ---------------------------------------------------------------------------
// Static device scratch (allocation-free)
// ---------------------------------------------------------------------------
__device__ float g_Upad[127 * 127 * 128];     // [t][s][k-pad]   8.3 MB
__device__ float g_W1s[NPAD * 128];           // [pair][k-pad]   4.5 MB (sym-folded)
__device__ int   g_pmap[NPAD];                // pair -> i*128+j (pad -> 0)
__device__ float g_z0p[32 * 1024 * 128];      // split-K partials
__device__ float g_z0[1024 * 128];            // [b][k-pad]
__device__ float g_dz[1024 * 127 * 128];      // [b][t][k-pad]  66.6 MB

// ---------------------------------------------------------------------------
// f32x2 packed-FMA helpers (A-side pairs come from 16B-aligned smem loads)
// ---------------------------------------------------------------------------
__device__ __forceinline__ ull dup2(float x) {
    ull u;
    asm("mov.b64 %0, {%1, %1};" : "=l"(u) : "r"(__float_as_uint(x)));
    return u;
}
__device__ __forceinline__ void unpack2(ull u, float& lo, float& hi) {
    unsigned int a, b;
    asm("mov.b64 {%0, %1}, %2;" : "=r"(a), "=r"(b) : "l"(u));
    lo = __uint_as_float(a); hi = __uint_as_float(b);
}
__device__ __forceinline__ void fma2(ull& d, ull a, ull b) {
    asm("fma.rn.f32x2 %0, %1, %2, %0;" : "+l"(d) : "l"(a), "l"(b));
}

// acc2[i2][j]: row-pair (ty*8+2*i2, +1), col tx*8+j. Arow/Brow 16B-aligned.
__device__ __forceinline__ void mma_step(ull acc2[4][8],
                                         const float* __restrict__ Arow,
                                         const float* __restrict__ Brow) {
    ulonglong2 aA = *(const ulonglong2*)(Arow);
    ulonglong2 aB = *(const ulonglong2*)(Arow + 4);
    float4 b0 = *(const float4*)(Brow);
    float4 b1 = *(const float4*)(Brow + 4);
    ull a2[4] = {aA.x, aA.y, aB.x, aB.y};
    ull bd[8];
    bd[0] = dup2(b0.x); bd[1] = dup2(b0.y); bd[2] = dup2(b0.z); bd[3] = dup2(b0.w);
    bd[4] = dup2(b1.x); bd[5] = dup2(b1.y); bd[6] = dup2(b1.z); bd[7] = dup2(b1.w);
#pragma unroll
    for (int i2 = 0; i2 < 4; i2++)
#pragma unroll
        for (int j = 0; j < 8; j++) fma2(acc2[i2][j], a2[i2], bd[j]);
}

// ---------------------------------------------------------------------------
// Merged builder: blocks [0,508) build U; [508,636) build W1s; [636,640) pmap.
// ---------------------------------------------------------------------------
__global__ void k_build(const float* __restrict__ W1) {
    int bx = blockIdx.x;
    int k = threadIdx.x;

    if (bx < 508) {                        // ---- U[t][s][k] ----
        int t = bx % 127;
        int s0 = (bx / 127) * 32;
        int s1 = s0 + 32 < 127 ? s0 + 32 : 127;
        float winf = (k < MM) ? W1[16256 * 127 + k] : 0.f;
        for (int s = s0; s < s1; s++) {
            float u = 0.f;
            if (k < MM) {
                if (s == t)
                    u = W1[(t * 127 + t) * 127 + k] - winf;
                else
                    u = W1[(t * 127 + s) * 127 + k]
                      + W1[(s * 127 + t) * 127 + k]
                      - W1[(16129 + s) * 127 + k];
            }
            g_Upad[(t * 127 + s) * 128 + k] = u;
        }
    } else if (bx < 636) {                 // ---- W1s[pair][k] (sym-folded) ----
        int i = bx - 508;                  // 0..127 (row of the pair)
        int base = i * 128 - (i * (i - 1)) / 2;   // pairs with i<=j
        for (int j = i; j < 128; j++) {
            int p = base + (j - i);
            float v = 0.f;
            if (k < 127) {
                if (i == 0 && j == 0)      v = W1[16256 * 127 + k];           // winf
                else if (i == 0)           v = W1[(16129 + j - 1) * 127 + k]; // Vt
                else if (i == j)           v = W1[((i - 1) * 127 + (i - 1)) * 127 + k];
                else                       v = W1[((i - 1) * 127 + (j - 1)) * 127 + k]
                                             + W1[((j - 1) * 127 + (i - 1)) * 127 + k];
            }
            g_W1s[p * 128 + k] = v;
        }
        // zero the pad rows (spread over the 128 W1s blocks)
        for (int p = NPAIR + i; p < NPAD; p += 128)
            g_W1s[p * 128 + k] = 0.f;
    } else {                               // ---- pmap ----
        int i = (bx - 636) * 32 + (k >> 2);        // 32 rows per block, 4 thr each
        int lane = k & 3;
        if (i < 128) {
            int base = i * 128 - (i * (i - 1)) / 2;
            for (int j = i + lane; j < 128; j += 4)
                g_pmap[base + (j - i)] = i * 128 + j;
        }
        if (bx == 636) {
            for (int p = NPAIR + k; p < NPAD; p += 128) g_pmap[p] = 0;
        }
    }
}

// ---------------------------------------------------------------------------
// z0 GEMM (symmetric-packed): [1024, 8704] @ [8704, 128], split-K=32.
// grid (8 m-tiles, 32 splits). K per split = 272 = 17 chunks of 16.
// A gathered from Theta via pair map (triangle read once).
// ---------------------------------------------------------------------------
__global__ void __launch_bounds__(256, 2) k_z0s(const float* __restrict__ Theta) {
    extern __shared__ float sm[];
    float* As = sm;                       // 2 * 16*132
    float* Bs = sm + 2 * 16 * 132;        // 2 * 16*128
    int* spmap = (int*)(sm + 2 * 16 * 132 + 2 * 16 * 128);   // 272 ints
    const int tid = threadIdx.x, tx = tid & 15, ty = tid >> 4;
    const int b0 = blockIdx.x * 128;
    const int kbase = blockIdx.y * KPER;

    for (int q = tid; q < KPER; q += 256) spmap[q] = g_pmap[kbase + q];
    __syncthreads();

    ull acc2[4][8];
#pragma unroll
    for (int i = 0; i < 4; i++)
#pragma unroll
        for (int j = 0; j < 8; j++) acc2[i][j] = 0ull;

    // prologue: chunk 0 (16 k-rows)
#pragma unroll
    for (int p = 0; p < 8; p++) {
        int i = tid + p * 256;            // 0..2047
        int kk = i & 15, bb = i >> 4;
        As[kk * 132 + bb] = Theta[(b0 + bb) * 16384 + spmap[kk]];
    }
#pragma unroll
    for (int p = 0; p < 8; p++) {
        int i = tid + p * 256;
        Bs[i] = g_W1s[(kbase + (i >> 7)) * 128 + (i & 127)];
    }
    __syncthreads();

    float pa[8], pb[8];
    for (int c = 0; c < 17; c++) {
        if (c < 16) {
            int kc = (c + 1) * 16;
#pragma unroll
            for (int p = 0; p < 8; p++) {
                int i = tid + p * 256;
                int kk = i & 15, bb = i >> 4;
                pa[p] = Theta[(b0 + bb) * 16384 + spmap[kc + kk]];
            }
#pragma unroll
            for (int p = 0; p < 8; p++) {
                int i = tid + p * 256;
                pb[p] = g_W1s[(kbase + kc + (i >> 7)) * 128 + (i & 127)];
            }
        }
        const float* Ab = As + (c & 1) * (16 * 132);
        const float* Bb = Bs + (c & 1) * (16 * 128);
#pragma unroll 8
        for (int s = 0; s < 16; s++)
            mma_step(acc2, Ab + s * 132 + ty * 8, Bb + s * 128 + tx * 8);
        if (c < 16) {
            float* An = As + ((c + 1) & 1) * (16 * 132);
            float* Bn = Bs + ((c + 1) & 1) * (16 * 128);
#pragma unroll
            for (int p = 0; p < 8; p++) {
                int i = tid + p * 256;
                An[(i & 15) * 132 + (i >> 4)] = pa[p];
            }
#pragma unroll
            for (int p = 0; p < 8; p++) {
                int i = tid + p * 256;
                Bn[i] = pb[p];
            }
            __syncthreads();
        }
    }
    float* outp = g_z0p + (blockIdx.y * 1024 + b0) * 128;
#pragma unroll
    for (int i2 = 0; i2 < 4; i2++) {
        float lo[8], hi[8];
#pragma unroll
        for (int j = 0; j < 8; j++) unpack2(acc2[i2][j], lo[j], hi[j]);
        float* p0 = outp + (ty * 8 + 2 * i2) * 128 + tx * 8;
        float* p1 = p0 + 128;
        *(float4*)p0       = make_float4(lo[0], lo[1], lo[2], lo[3]);
        *(float4*)(p0 + 4) = make_float4(lo[4], lo[5], lo[6], lo[7]);
        *(float4*)p1       = make_float4(hi[0], hi[1], hi[2], hi[3]);
        *(float4*)(p1 + 4) = make_float4(hi[4], hi[5], hi[6], hi[7]);
    }
}

// ---------------------------------------------------------------------------
// reduce split-K partials + bias
// ---------------------------------------------------------------------------
__global__ void k_z0red(const float* __restrict__ b1) {
    int idx = blockIdx.x * 256 + threadIdx.x;
    int k = idx & 127;
    float s = (k < 127) ? b1[k] : 0.f;
#pragma unroll
    for (int sp = 0; sp < 32; sp++) s += g_z0p[sp * 131072 + idx];
    g_z0[idx] = s;
}

// ---------------------------------------------------------------------------
// dz[b,t,k] = sum_s D[b,t,s]*U[t,s,k]; D on the fly (diag special case!)
// ---------------------------------------------------------------------------
__global__ void __launch_bounds__(256, 2) k_dz(const float* __restrict__ Theta) {
    extern __shared__ float sm[];
    float* Us = sm;            // 128*128
    float* Ds = sm + 16384;    // 2 * 32*132
    const int tid = threadIdx.x, tx = tid & 15, ty = tid >> 4;
    const int t = blockIdx.x, b0 = blockIdx.y * 128;

    {
        const float4* Usrc = (const float4*)(g_Upad + t * 16256);
        float4* Ud = (float4*)Us;
        for (int i = tid; i < 4064; i += 256) Ud[i] = Usrc[i];
        for (int i = 16256 + tid; i < 16384; i += 256) Us[i] = 0.f;
    }

    auto loadD = [&](int c, int p) -> float {
        int i = tid + p * 256;
        int s = i & 31, bb = i >> 5;
        int sg = c * 32 + s;
        if (sg >= 127) return 0.f;
        const float* Tb = Theta + (b0 + bb) * 16384;
        if (sg == t)
            return Tb[(t << 7) + t] - Tb[((t + 1) << 7) + (t + 1)];
        int g = sg + (sg >= t);
        return Tb[(t << 7) + g] - Tb[((t + 1) << 7) + g];
    };

#pragma unroll
    for (int p = 0; p < 16; p++) {
        int i = tid + p * 256;
        Ds[(i & 31) * 132 + (i >> 5)] = loadD(0, p);
    }
    __syncthreads();

    ull acc2[4][8];
#pragma unroll
    for (int i = 0; i < 4; i++)
#pragma unroll
        for (int j = 0; j < 8; j++) acc2[i][j] = 0ull;

    float pre[16];
    for (int c = 0; c < 4; c++) {
        if (c < 3) {
#pragma unroll
            for (int p = 0; p < 16; p++) pre[p] = loadD(c + 1, p);
        }
        const float* Db = Ds + (c & 1) * 4224;
        const float* Ub = Us + c * 32 * 128;
#pragma unroll 8
        for (int s = 0; s < 32; s++)
            mma_step(acc2, Db + s * 132 + ty * 8, Ub + s * 128 + tx * 8);
        if (c < 3) {
            float* Dn = Ds + ((c + 1) & 1) * 4224;
#pragma unroll
            for (int p = 0; p < 16; p++) {
                int i = tid + p * 256;
                Dn[(i & 31) * 132 + (i >> 5)] = pre[p];
            }
            __syncthreads();
        }
    }
#pragma unroll
    for (int i2 = 0; i2 < 4; i2++) {
        float lo[8], hi[8];
#pragma unroll
        for (int j = 0; j < 8; j++) unpack2(acc2[i2][j], lo[j], hi[j]);
        int bb0 = b0 + ty * 8 + 2 * i2;
        float* p0 = g_dz + (bb0 * 127 + t) * 128 + tx * 8;
        float* p1 = g_dz + ((bb0 + 1) * 127 + t) * 128 + tx * 8;
        *(float4*)p0       = make_float4(lo[0], lo[1], lo[2], lo[3]);
        *(float4*)(p0 + 4) = make_float4(lo[4], lo[5], lo[6], lo[7]);
        *(float4*)p1       = make_float4(hi[0], hi[1], hi[2], hi[3]);
        *(float4*)(p1 + 4) = make_float4(hi[4], hi[5], hi[6], hi[7]);
    }
}

// ---------------------------------------------------------------------------
// Fused: prefix+ReLU into smem h_T[k][t] (pad 132), GEMM h@W2 with W2
// streamed (double-buffered), bias, final out assembly (Theta symmetry).
// ---------------------------------------------------------------------------
__global__ void __launch_bounds__(256, 2) k_g2out(const float* __restrict__ Theta,
                                                  const float* __restrict__ W2,
                                                  const float* __restrict__ b2,
                                                  float* __restrict__ out) {
    extern __shared__ float sm[];
    float* Ht = sm;              // [k][t] pad 132; later reused as t12n stage [r][132]
    float* Ws = sm + 128 * 132;  // 2 * 32*128 W2 chunks
    const int tid = threadIdx.x, tx = tid & 15, ty = tid >> 4;
    const int b = blockIdx.x;

    if (tid < 128) {
        int k = tid;
        float z = g_z0[b * 128 + k];
        const float* dzp = g_dz + b * 127 * 128 + k;
        Ht[k * 132] = fmaxf(z, 0.f);
#pragma unroll 4
        for (int t = 1; t < 128; t++) {
            z += dzp[(t - 1) * 128];
            Ht[k * 132 + t] = fmaxf(z, 0.f);
        }
    } else {
        int t2 = tid - 128;
#pragma unroll
        for (int p = 0; p < 32; p++) {
            int i = t2 + p * 128;
            int kk = i >> 7, ss = i & 127;
            Ws[i] = (ss < 127) ? W2[kk * 127 + ss] : 0.f;
        }
    }
    __syncthreads();

    ull acc2[4][8];
#pragma unroll
    for (int i = 0; i < 4; i++)
#pragma unroll
        for (int j = 0; j < 8; j++) acc2[i][j] = 0ull;

    float pre[16];
    for (int c = 0; c < 4; c++) {
        if (c < 3) {
#pragma unroll
            for (int p = 0; p < 16; p++) {
                int i = tid + p * 256;
                int kk = (c + 1) * 32 + (i >> 7), ss = i & 127;
                pre[p] = (kk < 127 && ss < 127) ? W2[kk * 127 + ss] : 0.f;
            }
        }
        const float* Wb = Ws + (c & 1) * 4096;
#pragma unroll 8
        for (int s = 0; s < 32; s++)
            mma_step(acc2, Ht + (c * 32 + s) * 132 + ty * 8, Wb + s * 128 + tx * 8);
        if (c < 3) {
            float* Wn = Ws + ((c + 1) & 1) * 4096;
#pragma unroll
            for (int p = 0; p < 16; p++) {
                int i = tid + p * 256;
                Wn[i] = pre[p];
            }
            __syncthreads();
        }
    }
    __syncthreads();

    float b2v[8];
#pragma unroll
    for (int j = 0; j < 8; j++) {
        int ss = tx * 8 + j;
        b2v[j] = (ss < 127) ? b2[ss] : 0.f;
    }

#pragma unroll
    for (int i2 = 0; i2 < 4; i2++) {
        float lo[8], hi[8];
#pragma unroll
        for (int j = 0; j < 8; j++) unpack2(acc2[i2][j], lo[j], hi[j]);
        int r0 = ty * 8 + 2 * i2;
#pragma unroll
        for (int j = 0; j < 8; j++) {
            Ht[r0 * 132 + tx * 8 + j]       = lo[j] + b2v[j];
            Ht[(r0 + 1) * 132 + tx * 8 + j] = hi[j] + b2v[j];
        }
    }
    __syncthreads();

    const float* Tb = Theta + b * 16384;
    float* Ob = out + b * 16384;
    for (int idx4 = tid; idx4 < 4096; idx4 += 256) {
        int r = idx4 >> 5;
        int c0 = (idx4 & 31) * 4;
        float4 th4 = *(const float4*)(Tb + r * 128 + c0);
        float th[4] = {th4.x, th4.y, th4.z, th4.w};
        float o[4];
#pragma unroll
        for (int l = 0; l < 4; l++) {
            int c = c0 + l;
            if (r == c) {
                o[l] = th[l];
            } else {
                int T = r > c ? r : c;
                int m = r < c ? r : c;
                float tn = Ht[T * 132 + m];
                o[l] = th[l] + 129.f * (tn - th[l]);
            }
        }
        *(float4*)(Ob + r * 128 + c0) = make_float4(o[0], o[1], o[2], o[3]);
    }
}

// ---------------------------------------------------------------------------
// Launch
// ---------------------------------------------------------------------------
extern "C" void kernel_launch(void* const* d_in, const int* in_sizes, int n_in,
                              void* d_out, int out_size) {
    const float* Theta = (const float*)d_in[0];
    const float* W1    = (const float*)d_in[1];
    const float* b1    = (const float*)d_in[2];
    const float* W2    = (const float*)d_in[3];
    const float* b2    = (const float*)d_in[4];
    float* out = (float*)d_out;
    (void)in_sizes; (void)n_in; (void)out_size;

    const int SM_Z0 = (2 * 16 * 132 + 2 * 16 * 128) * 4 + KPER * 4;  // 34368
    const int SM_DZ = (16384 + 2 * 32 * 132) * 4;                    // 99328
    const int SM_G2 = (128 * 132 + 2 * 32 * 128) * 4;                // 100352
    cudaFuncSetAttribute(k_z0s,   cudaFuncAttributeMaxDynamicSharedMemorySize, SM_Z0);
    cudaFuncSetAttribute(k_dz,    cudaFuncAttributeMaxDynamicSharedMemorySize, SM_DZ);
    cudaFuncSetAttribute(k_g2out, cudaFuncAttributeMaxDynamicSharedMemorySize, SM_G2);

    k_build<<<640, 128>>>(W1);
    k_z0s<<<dim3(8, 32), 256, SM_Z0>>>(Theta);
    k_z0red<<<512, 256>>>(b1);
    k_dz<<<dim3(127, 8), 256, SM_DZ>>>(Theta);
    k_g2out<<<1024, 256, SM_G2>>>(Theta, W2, b2, out);
}

// round 9
// speedup vs baseline: 3.2331x; 1.1379x over previous
#include <cuda_runtime.h>

#define BB 1024
#define PP 128
#define MM 127

typedef unsigned long long ull;

#define NPAIR 8256          // 128*129/2
#define KSPLIT 32
#define KPER 272            // per-split pair count (17 chunks of 16); 32*272 = 8704
#define NPAD (KSPLIT * KPER)

// ---------------------------------------------------------------------------
// Static device scratch (allocation-free)
// ---------------------------------------------------------------------------
__device__ float g_Upad[127 * 127 * 128];     // [t][s][k-pad]   8.3 MB
__device__ float g_W1s[NPAD * 128];           // [pair][k-pad]   4.5 MB (sym-folded)
__device__ int   g_pmap[NPAD];                // pair -> i*128+j (pad -> 0)
__device__ float g_z0p[32 * 1024 * 128];      // split-K partials
__device__ float g_z0[1024 * 128];            // [b][k-pad]
__device__ float g_dz[1024 * 127 * 128];      // [b][t][k-pad]  66.6 MB

// ---------------------------------------------------------------------------
// f32x2 packed-FMA helpers
// ---------------------------------------------------------------------------
__device__ __forceinline__ ull dup2(float x) {
    ull u;
    asm("mov.b64 %0, {%1, %1};" : "=l"(u) : "r"(__float_as_uint(x)));
    return u;
}
__device__ __forceinline__ void unpack2(ull u, float& lo, float& hi) {
    unsigned int a, b;
    asm("mov.b64 {%0, %1}, %2;" : "=r"(a), "=r"(b) : "l"(u));
    lo = __uint_as_float(a); hi = __uint_as_float(b);
}
__device__ __forceinline__ void fma2(ull& d, ull a, ull b) {
    asm("fma.rn.f32x2 %0, %1, %2, %0;" : "+l"(d) : "l"(a), "l"(b));
}

// 512-thread mapping: tx = tid&31 (4 cols), ty = tid>>5 (8 rows).
// Within a warp ty is constant -> A-side LDS is a free broadcast.
// acc2[i2][j]: rows ty*8+2*i2{,+1}, col tx*4+j.
__device__ __forceinline__ void mma_step512(ull acc2[4][4],
                                            const float* __restrict__ Arow,
                                            const float* __restrict__ Bcol) {
    ulonglong2 aA = *(const ulonglong2*)(Arow);       // rows +0..3 packed
    ulonglong2 aB = *(const ulonglong2*)(Arow + 4);   // rows +4..7 packed
    float4 b = *(const float4*)(Bcol);
    ull a2[4] = {aA.x, aA.y, aB.x, aB.y};
    ull bd[4] = {dup2(b.x), dup2(b.y), dup2(b.z), dup2(b.w)};
#pragma unroll
    for (int i2 = 0; i2 < 4; i2++)
#pragma unroll
        for (int j = 0; j < 4; j++) fma2(acc2[i2][j], a2[i2], bd[j]);
}

// ---------------------------------------------------------------------------
// Merged builder: blocks [0,508) build U; [508,636) build W1s; [636,640) pmap.
// ---------------------------------------------------------------------------
__global__ void k_build(const float* __restrict__ W1) {
    int bx = blockIdx.x;
    int k = threadIdx.x;

    if (bx < 508) {                        // ---- U[t][s][k] ----
        int t = bx % 127;
        int s0 = (bx / 127) * 32;
        int s1 = s0 + 32 < 127 ? s0 + 32 : 127;
        float winf = (k < MM) ? W1[16256 * 127 + k] : 0.f;
        for (int s = s0; s < s1; s++) {
            float u = 0.f;
            if (k < MM) {
                if (s == t)
                    u = W1[(t * 127 + t) * 127 + k] - winf;
                else
                    u = W1[(t * 127 + s) * 127 + k]
                      + W1[(s * 127 + t) * 127 + k]
                      - W1[(16129 + s) * 127 + k];
            }
            g_Upad[(t * 127 + s) * 128 + k] = u;
        }
    } else if (bx < 636) {                 // ---- W1s[pair][k] (sym-folded) ----
        int i = bx - 508;
        int base = i * 128 - (i * (i - 1)) / 2;
        for (int j = i; j < 128; j++) {
            int p = base + (j - i);
            float v = 0.f;
            if (k < 127) {
                if (i == 0 && j == 0)      v = W1[16256 * 127 + k];
                else if (i == 0)           v = W1[(16129 + j - 1) * 127 + k];
                else if (i == j)           v = W1[((i - 1) * 127 + (i - 1)) * 127 + k];
                else                       v = W1[((i - 1) * 127 + (j - 1)) * 127 + k]
                                             + W1[((j - 1) * 127 + (i - 1)) * 127 + k];
            }
            g_W1s[p * 128 + k] = v;
        }
        for (int p = NPAIR + i; p < NPAD; p += 128)
            g_W1s[p * 128 + k] = 0.f;
    } else {                               // ---- pmap ----
        int i = (bx - 636) * 32 + (k >> 2);
        int lane = k & 3;
        if (i < 128) {
            int base = i * 128 - (i * (i - 1)) / 2;
            for (int j = i + lane; j < 128; j += 4)
                g_pmap[base + (j - i)] = i * 128 + j;
        }
        if (bx == 636) {
            for (int p = NPAIR + k; p < NPAD; p += 128) g_pmap[p] = 0;
        }
    }
}

// ---------------------------------------------------------------------------
// z0 GEMM (symmetric-packed): [1024, 8704] @ [8704, 128], split-K=32.
// grid (8, 32), 512 threads.
// ---------------------------------------------------------------------------
__global__ void __launch_bounds__(512, 2) k_z0s(const float* __restrict__ Theta) {
    extern __shared__ float sm[];
    float* As = sm;                       // 2 * 16*132
    float* Bs = sm + 2 * 16 * 132;        // 2 * 16*128
    int* spmap = (int*)(sm + 2 * 16 * 132 + 2 * 16 * 128);   // 272 ints
    const int tid = threadIdx.x, tx = tid & 31, ty = tid >> 5;
    const int b0 = blockIdx.x * 128;
    const int kbase = blockIdx.y * KPER;

    for (int q = tid; q < KPER; q += 512) spmap[q] = g_pmap[kbase + q];
    __syncthreads();

    ull acc2[4][4];
#pragma unroll
    for (int i = 0; i < 4; i++)
#pragma unroll
        for (int j = 0; j < 4; j++) acc2[i][j] = 0ull;

#pragma unroll
    for (int p = 0; p < 4; p++) {
        int i = tid + p * 512;            // 0..2047
        int kk = i & 15, bb = i >> 4;
        As[kk * 132 + bb] = Theta[(b0 + bb) * 16384 + spmap[kk]];
    }
#pragma unroll
    for (int p = 0; p < 4; p++) {
        int i = tid + p * 512;
        Bs[i] = g_W1s[(kbase + (i >> 7)) * 128 + (i & 127)];
    }
    __syncthreads();

    float pa[4], pb[4];
    for (int c = 0; c < 17; c++) {
        if (c < 16) {
            int kc = (c + 1) * 16;
#pragma unroll
            for (int p = 0; p < 4; p++) {
                int i = tid + p * 512;
                int kk = i & 15, bb = i >> 4;
                pa[p] = Theta[(b0 + bb) * 16384 + spmap[kc + kk]];
            }
#pragma unroll
            for (int p = 0; p < 4; p++) {
                int i = tid + p * 512;
                pb[p] = g_W1s[(kbase + kc + (i >> 7)) * 128 + (i & 127)];
            }
        }
        const float* Ab = As + (c & 1) * (16 * 132);
        const float* Bb = Bs + (c & 1) * (16 * 128);
#pragma unroll 8
        for (int s = 0; s < 16; s++)
            mma_step512(acc2, Ab + s * 132 + ty * 8, Bb + s * 128 + tx * 4);
        if (c < 16) {
            float* An = As + ((c + 1) & 1) * (16 * 132);
            float* Bn = Bs + ((c + 1) & 1) * (16 * 128);
#pragma unroll
            for (int p = 0; p < 4; p++) {
                int i = tid + p * 512;
                An[(i & 15) * 132 + (i >> 4)] = pa[p];
            }
#pragma unroll
            for (int p = 0; p < 4; p++) {
                int i = tid + p * 512;
                Bn[i] = pb[p];
            }
            __syncthreads();
        }
    }
    float* outp = g_z0p + (blockIdx.y * 1024 + b0) * 128;
#pragma unroll
    for (int i2 = 0; i2 < 4; i2++) {
        float lo[4], hi[4];
#pragma unroll
        for (int j = 0; j < 4; j++) unpack2(acc2[i2][j], lo[j], hi[j]);
        float* p0 = outp + (ty * 8 + 2 * i2) * 128 + tx * 4;
        *(float4*)p0         = make_float4(lo[0], lo[1], lo[2], lo[3]);
        *(float4*)(p0 + 128) = make_float4(hi[0], hi[1], hi[2], hi[3]);
    }
}

// ---------------------------------------------------------------------------
// reduce split-K partials + bias
// ---------------------------------------------------------------------------
__global__ void k_z0red(const float* __restrict__ b1) {
    int idx = blockIdx.x * 256 + threadIdx.x;
    int k = idx & 127;
    float s = (k < 127) ? b1[k] : 0.f;
#pragma unroll
    for (int sp = 0; sp < 32; sp++) s += g_z0p[sp * 131072 + idx];
    g_z0[idx] = s;
}

// ---------------------------------------------------------------------------
// dz[b,t,k] = sum_s D[b,t,s]*U[t,s,k]; D on the fly (diag special case!)
// grid (127, 8), 512 threads, U_t resident.
// ---------------------------------------------------------------------------
__global__ void __launch_bounds__(512, 2) k_dz(const float* __restrict__ Theta) {
    extern __shared__ float sm[];
    float* Us = sm;            // 128*128 (row 127 zeroed)
    float* Ds = sm + 16384;    // 2 * 32*132
    const int tid = threadIdx.x, tx = tid & 31, ty = tid >> 5;
    const int t = blockIdx.x, b0 = blockIdx.y * 128;

    {
        const float4* Usrc = (const float4*)(g_Upad + t * 16256);
        float4* Ud = (float4*)Us;
        for (int i = tid; i < 4064; i += 512) Ud[i] = Usrc[i];
        for (int i = 16256 + tid; i < 16384; i += 512) Us[i] = 0.f;
    }

    auto loadD = [&](int c, int p) -> float {
        int i = tid + p * 512;
        int s = i & 31, bb = i >> 5;
        int sg = c * 32 + s;
        if (sg >= 127) return 0.f;
        const float* Tb = Theta + (b0 + bb) * 16384;
        if (sg == t)
            return Tb[(t << 7) + t] - Tb[((t + 1) << 7) + (t + 1)];
        int g = sg + (sg >= t);
        return Tb[(t << 7) + g] - Tb[((t + 1) << 7) + g];
    };

#pragma unroll
    for (int p = 0; p < 8; p++) {
        int i = tid + p * 512;
        Ds[(i & 31) * 132 + (i >> 5)] = loadD(0, p);
    }
    __syncthreads();

    ull acc2[4][4];
#pragma unroll
    for (int i = 0; i < 4; i++)
#pragma unroll
        for (int j = 0; j < 4; j++) acc2[i][j] = 0ull;

    float pre[8];
    for (int c = 0; c < 4; c++) {
        if (c < 3) {
#pragma unroll
            for (int p = 0; p < 8; p++) pre[p] = loadD(c + 1, p);
        }
        const float* Db = Ds + (c & 1) * 4224;
        const float* Ub = Us + c * 32 * 128;
#pragma unroll 8
        for (int s = 0; s < 32; s++)
            mma_step512(acc2, Db + s * 132 + ty * 8, Ub + s * 128 + tx * 4);
        if (c < 3) {
            float* Dn = Ds + ((c + 1) & 1) * 4224;
#pragma unroll
            for (int p = 0; p < 8; p++) {
                int i = tid + p * 512;
                Dn[(i & 31) * 132 + (i >> 5)] = pre[p];
            }
            __syncthreads();
        }
    }
#pragma unroll
    for (int i2 = 0; i2 < 4; i2++) {
        float lo[4], hi[4];
#pragma unroll
        for (int j = 0; j < 4; j++) unpack2(acc2[i2][j], lo[j], hi[j]);
        int bb0 = b0 + ty * 8 + 2 * i2;
        float* p0 = g_dz + (bb0 * 127 + t) * 128 + tx * 4;
        float* p1 = g_dz + ((bb0 + 1) * 127 + t) * 128 + tx * 4;
        *(float4*)p0 = make_float4(lo[0], lo[1], lo[2], lo[3]);
        *(float4*)p1 = make_float4(hi[0], hi[1], hi[2], hi[3]);
    }
}

// ---------------------------------------------------------------------------
// Fused: prefix+ReLU into smem h_T[k][t] (pad 132), GEMM h@W2 streamed,
// bias, final out assembly (Theta symmetry). grid 1024, 512 threads.
// ---------------------------------------------------------------------------
__global__ void __launch_bounds__(512, 2) k_g2out(const float* __restrict__ Theta,
                                                  const float* __restrict__ W2,
                                                  const float* __restrict__ b2,
                                                  float* __restrict__ out) {
    extern __shared__ float sm[];
    float* Ht = sm;              // [k][t] pad 132; later t12n stage [r][132]
    float* Ws = sm + 128 * 132;  // 2 * 32*128 W2 chunks
    const int tid = threadIdx.x, tx = tid & 31, ty = tid >> 5;
    const int b = blockIdx.x;

    // Phase 1: threads 0-127 prefix+relu for k=tid; 128-511 load W2 chunk 0.
    if (tid < 128) {
        int k = tid;
        float z = g_z0[b * 128 + k];
        const float* dzp = g_dz + b * 127 * 128 + k;
        Ht[k * 132] = fmaxf(z, 0.f);
#pragma unroll 4
        for (int t = 1; t < 128; t++) {
            z += dzp[(t - 1) * 128];
            Ht[k * 132 + t] = fmaxf(z, 0.f);
        }
    } else {
        for (int i = tid - 128; i < 4096; i += 384) {
            int kk = i >> 7, ss = i & 127;
            Ws[i] = (ss < 127) ? W2[kk * 127 + ss] : 0.f;
        }
    }
    __syncthreads();

    ull acc2[4][4];
#pragma unroll
    for (int i = 0; i < 4; i++)
#pragma unroll
        for (int j = 0; j < 4; j++) acc2[i][j] = 0ull;

    float pre[8];
    for (int c = 0; c < 4; c++) {
        if (c < 3) {
#pragma unroll
            for (int p = 0; p < 8; p++) {
                int i = tid + p * 512;
                int kk = (c + 1) * 32 + (i >> 7), ss = i & 127;
                pre[p] = (kk < 127 && ss < 127) ? W2[kk * 127 + ss] : 0.f;
            }
        }
        const float* Wb = Ws + (c & 1) * 4096;
#pragma unroll 8
        for (int s = 0; s < 32; s++)
            mma_step512(acc2, Ht + (c * 32 + s) * 132 + ty * 8, Wb + s * 128 + tx * 4);
        if (c < 3) {
            float* Wn = Ws + ((c + 1) & 1) * 4096;
#pragma unroll
            for (int p = 0; p < 8; p++) {
                int i = tid + p * 512;
                Wn[i] = pre[p];
            }
            __syncthreads();
        }
    }
    __syncthreads();   // all Ht reads done before reuse as stage

    float b2v[4];
#pragma unroll
    for (int j = 0; j < 4; j++) {
        int ss = tx * 4 + j;
        b2v[j] = (ss < 127) ? b2[ss] : 0.f;
    }

    // stage t12n tile into Ht: [r][132] (rows = t, cols = s)
#pragma unroll
    for (int i2 = 0; i2 < 4; i2++) {
        float lo[4], hi[4];
#pragma unroll
        for (int j = 0; j < 4; j++) unpack2(acc2[i2][j], lo[j], hi[j]);
        int r0 = ty * 8 + 2 * i2;
#pragma unroll
        for (int j = 0; j < 4; j++) {
            Ht[r0 * 132 + tx * 4 + j]       = lo[j] + b2v[j];
            Ht[(r0 + 1) * 132 + tx * 4 + j] = hi[j] + b2v[j];
        }
    }
    __syncthreads();

    // out[b,r,c]: diag = th; off-diag = th + 129*(t12n[max][min] - th)
    const float* Tb = Theta + b * 16384;
    float* Ob = out + b * 16384;
    for (int idx4 = tid; idx4 < 4096; idx4 += 512) {
        int r = idx4 >> 5;
        int c0 = (idx4 & 31) * 4;
        float4 th4 = *(const float4*)(Tb + r * 128 + c0);
        float th[4] = {th4.x, th4.y, th4.z, th4.w};
        float o[4];
#pragma unroll
        for (int l = 0; l < 4; l++) {
            int c = c0 + l;
            if (r == c) {
                o[l] = th[l];
            } else {
                int T = r > c ? r : c;
                int m = r < c ? r : c;
                float tn = Ht[T * 132 + m];
                o[l] = th[l] + 129.f * (tn - th[l]);
            }
        }
        *(float4*)(Ob + r * 128 + c0) = make_float4(o[0], o[1], o[2], o[3]);
    }
}

// ---------------------------------------------------------------------------
// Launch
// ---------------------------------------------------------------------------
extern "C" void kernel_launch(void* const* d_in, const int* in_sizes, int n_in,
                              void* d_out, int out_size) {
    const float* Theta = (const float*)d_in[0];
    const float* W1    = (const float*)d_in[1];
    const float* b1    = (const float*)d_in[2];
    const float* W2    = (const float*)d_in[3];
    const float* b2    = (const float*)d_in[4];
    float* out = (float*)d_out;
    (void)in_sizes; (void)n_in; (void)out_size;

    const int SM_Z0 = (2 * 16 * 132 + 2 * 16 * 128) * 4 + KPER * 4;  // 34368
    const int SM_DZ = (16384 + 2 * 32 * 132) * 4;                    // 99328
    const int SM_G2 = (128 * 132 + 2 * 32 * 128) * 4;                // 100352
    cudaFuncSetAttribute(k_z0s,   cudaFuncAttributeMaxDynamicSharedMemorySize, SM_Z0);
    cudaFuncSetAttribute(k_dz,    cudaFuncAttributeMaxDynamicSharedMemorySize, SM_DZ);
    cudaFuncSetAttribute(k_g2out, cudaFuncAttributeMaxDynamicSharedMemorySize, SM_G2);

    k_build<<<640, 128>>>(W1);
    k_z0s<<<dim3(8, 32), 512, SM_Z0>>>(Theta);
    k_z0red<<<512, 256>>>(b1);
    k_dz<<<dim3(127, 8), 512, SM_DZ>>>(Theta);
    k_g2out<<<1024, 512, SM_G2>>>(Theta, W2, b2, out);
}

// round 11
// speedup vs baseline: 3.7635x; 1.1641x over previous
#include <cuda_runtime.h>

#define BB 1024
#define PP 128
#define MM 127

typedef unsigned long long ull;

#define NPAIR 8256          // 128*129/2
#define KSPLIT 32
#define KPER 272            // per-split pair count (17 chunks of 16); 32*272 = 8704
#define NPAD (KSPLIT * KPER)

// ---------------------------------------------------------------------------
// Static device scratch (allocation-free)
// ---------------------------------------------------------------------------
__device__ float g_Upad[127 * 127 * 128];     // [t][s][k-pad]   8.3 MB
__device__ float g_W1s[NPAD * 128];           // [pair][k-pad]   4.5 MB (sym-folded)
__device__ int   g_pmap[NPAD];                // pair -> i*128+j (pad -> 0)
__device__ float g_z0p[32 * 1024 * 128];      // split-K partials
__device__ float g_z0[1024 * 128];            // [b][k-pad]
__device__ float g_dz[1024 * 127 * 128];      // [b][t][k-pad]  66.6 MB

// ---------------------------------------------------------------------------
// f32x2 packed-FMA helpers
// ---------------------------------------------------------------------------
__device__ __forceinline__ ull dup2(float x) {
    ull u; asm("mov.b64 %0, {%1, %1};" : "=l"(u) : "r"(__float_as_uint(x))); return u;
}
__device__ __forceinline__ void unpack2(ull u, float& lo, float& hi) {
    unsigned int a, b;
    asm("mov.b64 {%0, %1}, %2;" : "=r"(a), "=r"(b) : "l"(u));
    lo = __uint_as_float(a); hi = __uint_as_float(b);
}
__device__ __forceinline__ void fma2(ull& d, ull a, ull b) {
    asm("fma.rn.f32x2 %0, %1, %2, %0;" : "+l"(d) : "l"(a), "l"(b));
}

// 512-thread mapping: tx = tid&31 (4 cols), ty = tid>>5 (8 rows).
// acc2[i2][j]: rows ty*8+2*i2{,+1}, col tx*4+j. A-side LDS is warp-broadcast.
__device__ __forceinline__ void mma_step512(ull acc2[4][4],
                                            const float* __restrict__ Arow,
                                            const float* __restrict__ Bcol) {
    ulonglong2 aA = *(const ulonglong2*)(Arow);
    ulonglong2 aB = *(const ulonglong2*)(Arow + 4);
    float4 b = *(const float4*)(Bcol);
    ull a2[4] = {aA.x, aA.y, aB.x, aB.y};
    ull bd[4] = {dup2(b.x), dup2(b.y), dup2(b.z), dup2(b.w)};
#pragma unroll
    for (int i2 = 0; i2 < 4; i2++)
#pragma unroll
        for (int j = 0; j < 4; j++) fma2(acc2[i2][j], a2[i2], bd[j]);
}

// ---------------------------------------------------------------------------
// Merged builder: blocks [0,508) build U; [508,636) build W1s; [636,640) pmap.
// ---------------------------------------------------------------------------
__global__ void k_build(const float* __restrict__ W1) {
    int bx = blockIdx.x;
    int k = threadIdx.x;

    if (bx < 508) {                        // ---- U[t][s][k] ----
        int t = bx % 127;
        int s0 = (bx / 127) * 32;
        int s1 = s0 + 32 < 127 ? s0 + 32 : 127;
        float winf = (k < MM) ? W1[16256 * 127 + k] : 0.f;
        for (int s = s0; s < s1; s++) {
            float u = 0.f;
            if (k < MM) {
                if (s == t)
                    u = W1[(t * 127 + t) * 127 + k] - winf;
                else
                    u = W1[(t * 127 + s) * 127 + k]
                      + W1[(s * 127 + t) * 127 + k]
                      - W1[(16129 + s) * 127 + k];
            }
            g_Upad[(t * 127 + s) * 128 + k] = u;
        }
    } else if (bx < 636) {                 // ---- W1s[pair][k] (sym-folded) ----
        int i = bx - 508;
        int base = i * 128 - (i * (i - 1)) / 2;
        for (int j = i; j < 128; j++) {
            int p = base + (j - i);
            float v = 0.f;
            if (k < 127) {
                if (i == 0 && j == 0)      v = W1[16256 * 127 + k];
                else if (i == 0)           v = W1[(16129 + j - 1) * 127 + k];
                else if (i == j)           v = W1[((i - 1) * 127 + (i - 1)) * 127 + k];
                else                       v = W1[((i - 1) * 127 + (j - 1)) * 127 + k]
                                             + W1[((j - 1) * 127 + (i - 1)) * 127 + k];
            }
            g_W1s[p * 128 + k] = v;
        }
        for (int p = NPAIR + i; p < NPAD; p += 128)
            g_W1s[p * 128 + k] = 0.f;
    } else {                               // ---- pmap ----
        int i = (bx - 636) * 32 + (k >> 2);
        int lane = k & 3;
        if (i < 128) {
            int base = i * 128 - (i * (i - 1)) / 2;
            for (int j = i + lane; j < 128; j += 4)
                g_pmap[base + (j - i)] = i * 128 + j;
        }
        if (bx == 636) {
            for (int p = NPAIR + k; p < NPAD; p += 128) g_pmap[p] = 0;
        }
    }
}

// ---------------------------------------------------------------------------
// z0 GEMM (symmetric-packed): [1024, 8704] @ [8704, 128], split-K=32.
// ---------------------------------------------------------------------------
__global__ void __launch_bounds__(512, 2) k_z0s(const float* __restrict__ Theta) {
    extern __shared__ float sm[];
    float* As = sm;
    float* Bs = sm + 2 * 16 * 132;
    int* spmap = (int*)(sm + 2 * 16 * 132 + 2 * 16 * 128);
    const int tid = threadIdx.x, tx = tid & 31, ty = tid >> 5;
    const int b0 = blockIdx.x * 128;
    const int kbase = blockIdx.y * KPER;

    for (int q = tid; q < KPER; q += 512) spmap[q] = g_pmap[kbase + q];
    __syncthreads();

    ull acc2[4][4];
#pragma unroll
    for (int i = 0; i < 4; i++)
#pragma unroll
        for (int j = 0; j < 4; j++) acc2[i][j] = 0ull;

#pragma unroll
    for (int p = 0; p < 4; p++) {
        int i = tid + p * 512;
        int kk = i & 15, bb = i >> 4;
        As[kk * 132 + bb] = Theta[(b0 + bb) * 16384 + spmap[kk]];
    }
#pragma unroll
    for (int p = 0; p < 4; p++) {
        int i = tid + p * 512;
        Bs[i] = g_W1s[(kbase + (i >> 7)) * 128 + (i & 127)];
    }
    __syncthreads();

    float pa[4], pb[4];
    for (int c = 0; c < 17; c++) {
        if (c < 16) {
            int kc = (c + 1) * 16;
#pragma unroll
            for (int p = 0; p < 4; p++) {
                int i = tid + p * 512;
                int kk = i & 15, bb = i >> 4;
                pa[p] = Theta[(b0 + bb) * 16384 + spmap[kc + kk]];
            }
#pragma unroll
            for (int p = 0; p < 4; p++) {
                int i = tid + p * 512;
                pb[p] = g_W1s[(kbase + kc + (i >> 7)) * 128 + (i & 127)];
            }
        }
        const float* Ab = As + (c & 1) * (16 * 132);
        const float* Bb = Bs + (c & 1) * (16 * 128);
#pragma unroll 8
        for (int s = 0; s < 16; s++)
            mma_step512(acc2, Ab + s * 132 + ty * 8, Bb + s * 128 + tx * 4);
        if (c < 16) {
            float* An = As + ((c + 1) & 1) * (16 * 132);
            float* Bn = Bs + ((c + 1) & 1) * (16 * 128);
#pragma unroll
            for (int p = 0; p < 4; p++) {
                int i = tid + p * 512;
                An[(i & 15) * 132 + (i >> 4)] = pa[p];
            }
#pragma unroll
            for (int p = 0; p < 4; p++) {
                int i = tid + p * 512;
                Bn[i] = pb[p];
            }
            __syncthreads();
        }
    }
    float* outp = g_z0p + (blockIdx.y * 1024 + b0) * 128;
#pragma unroll
    for (int i2 = 0; i2 < 4; i2++) {
        float lo[4], hi[4];
#pragma unroll
        for (int j = 0; j < 4; j++) unpack2(acc2[i2][j], lo[j], hi[j]);
        float* p0 = outp + (ty * 8 + 2 * i2) * 128 + tx * 4;
        *(float4*)p0         = make_float4(lo[0], lo[1], lo[2], lo[3]);
        *(float4*)(p0 + 128) = make_float4(hi[0], hi[1], hi[2], hi[3]);
    }
}

// ---------------------------------------------------------------------------
// reduce split-K partials + bias
// ---------------------------------------------------------------------------
__global__ void k_z0red(const float* __restrict__ b1) {
    int idx = blockIdx.x * 256 + threadIdx.x;
    int k = idx & 127;
    float s = (k < 127) ? b1[k] : 0.f;
#pragma unroll
    for (int sp = 0; sp < 32; sp++) s += g_z0p[sp * 131072 + idx];
    g_z0[idx] = s;
}

// ---------------------------------------------------------------------------
// dz[b,t,k] = sum_s D[b,t,s]*U[t,s,k]; D on the fly (diag special case!)
// ---------------------------------------------------------------------------
__global__ void __launch_bounds__(512, 2) k_dz(const float* __restrict__ Theta) {
    extern __shared__ float sm[];
    float* Us = sm;            // 128*128 (row 127 zeroed)
    float* Ds = sm + 16384;    // 2 * 32*132
    const int tid = threadIdx.x, tx = tid & 31, ty = tid >> 5;
    const int t = blockIdx.x, b0 = blockIdx.y * 128;

    {
        const float4* Usrc = (const float4*)(g_Upad + t * 16256);
        float4* Ud = (float4*)Us;
        for (int i = tid; i < 4064; i += 512) Ud[i] = Usrc[i];
        for (int i = 16256 + tid; i < 16384; i += 512) Us[i] = 0.f;
    }

    auto loadD = [&](int c, int p) -> float {
        int i = tid + p * 512;
        int s = i & 31, bb = i >> 5;
        int sg = c * 32 + s;
        if (sg >= 127) return 0.f;
        const float* Tb = Theta + (b0 + bb) * 16384;
        if (sg == t)
            return Tb[(t << 7) + t] - Tb[((t + 1) << 7) + (t + 1)];
        int g = sg + (sg >= t);
        return Tb[(t << 7) + g] - Tb[((t + 1) << 7) + g];
    };

#pragma unroll
    for (int p = 0; p < 8; p++) {
        int i = tid + p * 512;
        Ds[(i & 31) * 132 + (i >> 5)] = loadD(0, p);
    }
    __syncthreads();

    ull acc2[4][4];
#pragma unroll
    for (int i = 0; i < 4; i++)
#pragma unroll
        for (int j = 0; j < 4; j++) acc2[i][j] = 0ull;

    float pre[8];
    for (int c = 0; c < 4; c++) {
        if (c < 3) {
#pragma unroll
            for (int p = 0; p < 8; p++) pre[p] = loadD(c + 1, p);
        }
        const float* Db = Ds + (c & 1) * 4224;
        const float* Ub = Us + c * 32 * 128;
#pragma unroll 8
        for (int s = 0; s < 32; s++)
            mma_step512(acc2, Db + s * 132 + ty * 8, Ub + s * 128 + tx * 4);
        if (c < 3) {
            float* Dn = Ds + ((c + 1) & 1) * 4224;
#pragma unroll
            for (int p = 0; p < 8; p++) {
                int i = tid + p * 512;
                Dn[(i & 31) * 132 + (i >> 5)] = pre[p];
            }
            __syncthreads();
        }
    }
#pragma unroll
    for (int i2 = 0; i2 < 4; i2++) {
        float lo[4], hi[4];
#pragma unroll
        for (int j = 0; j < 4; j++) unpack2(acc2[i2][j], lo[j], hi[j]);
        int bb0 = b0 + ty * 8 + 2 * i2;
        float* p0 = g_dz + (bb0 * 127 + t) * 128 + tx * 4;
        float* p1 = g_dz + ((bb0 + 1) * 127 + t) * 128 + tx * 4;
        *(float4*)p0 = make_float4(lo[0], lo[1], lo[2], lo[3]);
        *(float4*)p1 = make_float4(hi[0], hi[1], hi[2], hi[3]);
    }
}

// ---------------------------------------------------------------------------
// Fused: SEGMENTED prefix+ReLU into smem h_T[k][t] (4 segments of 32 t, all
// 512 threads active), GEMM h@W2 streamed, bias, out assembly (Theta symmetry).
// smem = 128*132 (Ht) + 2*32*128 (Ws) + 512 (carry) floats = 102400 B.
// ---------------------------------------------------------------------------
__global__ void __launch_bounds__(512, 2) k_g2out(const float* __restrict__ Theta,
                                                  const float* __restrict__ W2,
                                                  const float* __restrict__ b2,
                                                  float* __restrict__ out) {
    extern __shared__ float sm[];
    float* Ht  = sm;                       // [k][t] pad 132; later t12n stage
    float* Ws  = sm + 128 * 132;           // 2 * 32*128 W2 chunks
    float* car = sm + 128 * 132 + 8192;    // [seg][k] 4*128
    const int tid = threadIdx.x, tx = tid & 31, ty = tid >> 5;
    const int b = blockIdx.x;

    // Phase 0a: all threads load W2 chunk 0 into buffer 0.
#pragma unroll
    for (int p = 0; p < 8; p++) {
        int i = tid + p * 512;
        int kk = i >> 7, ss = i & 127;
        Ws[i] = (ss < 127) ? W2[kk * 127 + ss] : 0.f;
    }

    // Phase 0b: segmented prefix partials. (k, seg) = (tid&127, tid>>7).
    {
        const int k = tid & 127, seg = tid >> 7, T0 = seg * 32;
        const float* dzp = g_dz + (size_t)b * 127 * 128 + k;
        float acc = 0.f;
#pragma unroll 4
        for (int tt = 0; tt < 32; tt++) {
            Ht[k * 132 + T0 + tt] = acc;
            int c = T0 + tt;
            if (c < 127) acc += dzp[c * 128];
        }
        car[seg * 128 + k] = acc;
    }
    __syncthreads();

    // Phase 0c: carries (exclusive scan over 4 segments, per k).
    if (tid < 128) {
        float c0 = g_z0[b * 128 + tid];
        float c1 = c0 + car[0 * 128 + tid];
        float c2 = c1 + car[1 * 128 + tid];
        float c3 = c2 + car[2 * 128 + tid];
        car[0 * 128 + tid] = c0;
        car[1 * 128 + tid] = c1;
        car[2 * 128 + tid] = c2;
        car[3 * 128 + tid] = c3;
    }
    __syncthreads();

    // Phase 0d: add carry + ReLU in place.
    {
        const int k = tid & 127, seg = tid >> 7, T0 = seg * 32;
        float C = car[seg * 128 + k];
#pragma unroll 4
        for (int tt = 0; tt < 32; tt++) {
            float v = C + Ht[k * 132 + T0 + tt];
            Ht[k * 132 + T0 + tt] = fmaxf(v, 0.f);
        }
    }
    __syncthreads();

    ull acc2[4][4];
#pragma unroll
    for (int i = 0; i < 4; i++)
#pragma unroll
        for (int j = 0; j < 4; j++) acc2[i][j] = 0ull;

    float pre[8];
    for (int c = 0; c < 4; c++) {
        if (c < 3) {
#pragma unroll
            for (int p = 0; p < 8; p++) {
                int i = tid + p * 512;
                int kk = (c + 1) * 32 + (i >> 7), ss = i & 127;
                pre[p] = (kk < 127 && ss < 127) ? W2[kk * 127 + ss] : 0.f;
            }
        }
        const float* Wb = Ws + (c & 1) * 4096;
#pragma unroll 8
        for (int s = 0; s < 32; s++)
            mma_step512(acc2, Ht + (c * 32 + s) * 132 + ty * 8, Wb + s * 128 + tx * 4);
        if (c < 3) {
            float* Wn = Ws + ((c + 1) & 1) * 4096;
#pragma unroll
            for (int p = 0; p < 8; p++) {
                int i = tid + p * 512;
                Wn[i] = pre[p];
            }
            __syncthreads();
        }
    }
    __syncthreads();   // all Ht reads done before reuse as stage

    float b2v[4];
#pragma unroll
    for (int j = 0; j < 4; j++) {
        int ss = tx * 4 + j;
        b2v[j] = (ss < 127) ? b2[ss] : 0.f;
    }

    // stage t12n tile into Ht: [r][132] (rows = t, cols = s)
#pragma unroll
    for (int i2 = 0; i2 < 4; i2++) {
        float lo[4], hi[4];
#pragma unroll
        for (int j = 0; j < 4; j++) unpack2(acc2[i2][j], lo[j], hi[j]);
        int r0 = ty * 8 + 2 * i2;
#pragma unroll
        for (int j = 0; j < 4; j++) {
            Ht[r0 * 132 + tx * 4 + j]       = lo[j] + b2v[j];
            Ht[(r0 + 1) * 132 + tx * 4 + j] = hi[j] + b2v[j];
        }
    }
    __syncthreads();

    // out[b,r,c]: diag = th; off-diag = th + 129*(t12n[max][min] - th)
    const float* Tb = Theta + (size_t)b * 16384;
    float* Ob = out + (size_t)b * 16384;
    for (int idx4 = tid; idx4 < 4096; idx4 += 512) {
        int r = idx4 >> 5;
        int c0 = (idx4 & 31) * 4;
        float4 th4 = *(const float4*)(Tb + r * 128 + c0);
        float th[4] = {th4.x, th4.y, th4.z, th4.w};
        float o[4];
#pragma unroll
        for (int l = 0; l < 4; l++) {
            int c = c0 + l;
            if (r == c) {
                o[l] = th[l];
            } else {
                int T = r > c ? r : c;
                int m = r < c ? r : c;
                float tn = Ht[T * 132 + m];
                o[l] = th[l] + 129.f * (tn - th[l]);
            }
        }
        *(float4*)(Ob + r * 128 + c0) = make_float4(o[0], o[1], o[2], o[3]);
    }
}

// ---------------------------------------------------------------------------
// Launch: fork/join so (z0s -> z0red) overlaps with dz. Dependencies:
// build -> {z0 chain, dz}; g2out after both.
// ---------------------------------------------------------------------------
extern "C" void kernel_launch(void* const* d_in, const int* in_sizes, int n_in,
                              void* d_out, int out_size) {
    const float* Theta = (const float*)d_in[0];
    const float* W1    = (const float*)d_in[1];
    const float* b1    = (const float*)d_in[2];
    const float* W2    = (const float*)d_in[3];
    const float* b2    = (const float*)d_in[4];
    float* out = (float*)d_out;
    (void)in_sizes; (void)n_in; (void)out_size;

    static cudaStream_t s_aux = nullptr;
    static cudaEvent_t ev_root = nullptr, ev_aux = nullptr;
    if (s_aux == nullptr) {                 // first call is outside capture
        cudaStreamCreateWithFlags(&s_aux, cudaStreamNonBlocking);
        cudaEventCreateWithFlags(&ev_root, cudaEventDisableTiming);
        cudaEventCreateWithFlags(&ev_aux, cudaEventDisableTiming);
    }

    const int SM_Z0 = (2 * 16 * 132 + 2 * 16 * 128) * 4 + KPER * 4;
    const int SM_DZ = (16384 + 2 * 32 * 132) * 4;                    // 99328
    const int SM_G2 = (128 * 132 + 2 * 32 * 128 + 512) * 4;          // 102400
    cudaFuncSetAttribute(k_z0s,   cudaFuncAttributeMaxDynamicSharedMemorySize, SM_Z0);
    cudaFuncSetAttribute(k_dz,    cudaFuncAttributeMaxDynamicSharedMemorySize, SM_DZ);
    cudaFuncSetAttribute(k_g2out, cudaFuncAttributeMaxDynamicSharedMemorySize, SM_G2);

    k_build<<<640, 128>>>(W1);

    // fork: aux stream runs the z0 chain concurrently with dz
    cudaEventRecord(ev_root, 0);
    cudaStreamWaitEvent(s_aux, ev_root, 0);
    k_z0s<<<dim3(8, 32), 512, SM_Z0, s_aux>>>(Theta);
    k_z0red<<<512, 256, 0, s_aux>>>(b1);
    cudaEventRecord(ev_aux, s_aux);

    k_dz<<<dim3(127, 8), 512, SM_DZ>>>(Theta);

    // join
    cudaStreamWaitEvent(0, ev_aux, 0);
    k_g2out<<<1024, 512, SM_G2>>>(Theta, W2, b2, out);
}